// round 10
// baseline (speedup 1.0000x reference)
#include <cuda_runtime.h>
#include <cuda_bf16.h>
#include <cuda_fp16.h>
#include <math.h>

#define HID 3072
#define HEADS 24
#define HD 128
#define MLPD 12288
#define RANK 32
#define TXTL 512
#define IMGL 2048
#define L_TOT 2560
#define EPSF 1e-6f

#define QKV_SZ 28311552ULL
#define PRJ_SZ 9437184ULL
#define MLP_SZ 37748736ULL

// ---------------- device scratch ----------------
__device__ __align__(16) float g_sv[HID];
__device__ __align__(16) float g_mod[2 * 6 * HID];
__device__ __align__(16) float g_xm[(size_t)L_TOT * HID];
__device__ __align__(16) float g_t[(size_t)L_TOT * RANK];
__device__ __align__(16) float g_qkv[(size_t)L_TOT * 3 * HID];
__device__ __align__(16) float g_q[(size_t)L_TOT * HID];
__device__ __align__(16) float g_k[(size_t)L_TOT * HID];
__device__ __align__(16) float g_v[(size_t)L_TOT * HID];
__device__ __align__(16) float g_attn[(size_t)L_TOT * HID];
__device__ __align__(16) float g_x1[(size_t)L_TOT * HID];
__device__ __align__(16) float g_h[(size_t)IMGL * MLPD];

// fp16 weights (single, rounded)
__device__ __align__(16) __half g_wq16[2 * QKV_SZ];
__device__ __align__(16) __half g_wp16[2 * PRJ_SZ];
__device__ __align__(16) __half g_w016[2 * MLP_SZ];
__device__ __align__(16) __half g_w216[2 * MLP_SZ];
// fp16 activations (hi/lo)
__device__ __align__(16) __half g_a2h[(size_t)L_TOT * HID], g_a2l[(size_t)L_TOT * HID];
__device__ __align__(16) __half g_f2h[(size_t)L_TOT * HID], g_f2l[(size_t)L_TOT * HID];
__device__ __align__(16) __half g_b2h[(size_t)IMGL * MLPD], g_b2l[(size_t)IMGL * MLPD];
// lora
__device__ __align__(16) __half g_t2h[(size_t)L_TOT * RANK], g_t2l[(size_t)L_TOT * RANK];
__device__ __align__(16) __half g_lu2h[(size_t)MLPD * RANK];

// ---------------- asm helpers ----------------
__device__ __forceinline__ unsigned smem_u32(const void* p) {
    unsigned a;
    asm("{ .reg .u64 t; cvta.to.shared.u64 t, %1; cvt.u32.u64 %0, t; }" : "=r"(a) : "l"(p));
    return a;
}
__device__ __forceinline__ void ldmx4(unsigned (&r)[4], unsigned a) {
    asm volatile("ldmatrix.sync.aligned.m8n8.x4.shared.b16 {%0,%1,%2,%3}, [%4];"
                 : "=r"(r[0]), "=r"(r[1]), "=r"(r[2]), "=r"(r[3]) : "r"(a));
}
__device__ __forceinline__ void ldmx2(unsigned (&r)[2], unsigned a) {
    asm volatile("ldmatrix.sync.aligned.m8n8.x2.shared.b16 {%0,%1}, [%2];"
                 : "=r"(r[0]), "=r"(r[1]) : "r"(a));
}
__device__ __forceinline__ void mmaH(float (&d)[4], const unsigned (&a)[4], const unsigned (&b)[2]) {
    asm volatile("mma.sync.aligned.m16n8k16.row.col.f32.f16.f16.f32 "
                 "{%0,%1,%2,%3},{%4,%5,%6,%7},{%8,%9},{%0,%1,%2,%3};"
                 : "+f"(d[0]), "+f"(d[1]), "+f"(d[2]), "+f"(d[3])
                 : "r"(a[0]), "r"(a[1]), "r"(a[2]), "r"(a[3]), "r"(b[0]), "r"(b[1]));
}
__device__ __forceinline__ void cpa16(unsigned d, const void* s) {
    asm volatile("cp.async.cg.shared.global [%0], [%1], 16;" :: "r"(d), "l"(s));
}
__device__ __forceinline__ void cpcommit() { asm volatile("cp.async.commit_group;"); }
template <int N>
__device__ __forceinline__ void cpwait() { asm volatile("cp.async.wait_group %0;" :: "n"(N)); }

__device__ __forceinline__ float gelu2(float x) {
    float u = 0.7978845608028654f * (x + 0.044715f * x * x * x);
    float e = __expf(2.f * u);
    float th = 1.f - 2.f / (e + 1.f);
    return 0.5f * x * (1.f + th);
}

// ---------------- conversions ----------------
__global__ void __launch_bounds__(256) convH16(const float* __restrict__ src,
                                               __half* __restrict__ dh, size_t n4) {
    size_t idx = (size_t)blockIdx.x * 256 + threadIdx.x;
    if (idx >= n4) return;
    float4 v = ((const float4*)src)[idx];
    __half h[4] = {__float2half_rn(v.x), __float2half_rn(v.y),
                   __float2half_rn(v.z), __float2half_rn(v.w)};
    ((uint2*)dh)[idx] = *(uint2*)h;
}

__global__ void __launch_bounds__(256) convHL16(const float* __restrict__ src,
                                                __half* __restrict__ dh,
                                                __half* __restrict__ dl, size_t n4) {
    size_t idx = (size_t)blockIdx.x * 256 + threadIdx.x;
    if (idx >= n4) return;
    float4 v = ((const float4*)src)[idx];
    float vv[4] = {v.x, v.y, v.z, v.w};
    __half h[4], l[4];
#pragma unroll
    for (int i = 0; i < 4; ++i) {
        h[i] = __float2half_rn(vv[i]);
        l[i] = __float2half_rn(vv[i] - __half2float(h[i]));
    }
    ((uint2*)dh)[idx] = *(uint2*)h;
    ((uint2*)dl)[idx] = *(uint2*)l;
}

__global__ void __launch_bounds__(256) convLU16(const float* __restrict__ LU,
                                                __half* __restrict__ dh, int N) {
    int idx = blockIdx.x * 256 + threadIdx.x;
    if (idx >= N * 32) return;
    int n = idx >> 5, c = idx & 31;
    dh[(size_t)n * 32 + c] = __float2half_rn(LU[(size_t)c * N + n]);
}

// ---------------- fp16 2-pass split-precision GEMM ----------------
// stage (pitch 80B): Ah 0, Al 10240, Bh 20480 ; stage = 30720
#define STG_B 30720
#define GEMM_SMEM (2 * STG_B)

template <int MODE>
__global__ void __launch_bounds__(256, 2) gemm16(
    const __half* __restrict__ Ah, const __half* __restrict__ Al,
    const __half* __restrict__ Bh,
    const __half* __restrict__ Th, const __half* __restrict__ Tl,
    const __half* __restrict__ LUh,
    const float* __restrict__ bias, const float* __restrict__ RES,
    const float* __restrict__ GATE, float* __restrict__ C,
    __half* __restrict__ AoH, __half* __restrict__ AoL,
    int M, int N, int K) {
    extern __shared__ char sm[];
    unsigned sbase = smem_u32(sm);
    int tid = threadIdx.x, lane = tid & 31, wid = tid >> 5;
    int wm = wid >> 2, wn = wid & 3;
    int bm = blockIdx.x * 128, bn = blockIdx.y * 128;
    int KC = K >> 5, TOT = KC + 1;

    float acc[4][4][4];
#pragma unroll
    for (int a = 0; a < 4; ++a)
#pragma unroll
        for (int b = 0; b < 4; ++b)
#pragma unroll
            for (int c = 0; c < 4; ++c) acc[a][b][c] = 0.f;

#define LOAD_STAGE(cc)                                                                   \
    {                                                                                    \
        int c_ = (cc);                                                                   \
        unsigned sb_ = sbase + (c_ & 1) * STG_B;                                         \
        const char* bases_[3];                                                           \
        size_t rb_; int ko_;                                                             \
        if (c_ < KC) {                                                                   \
            bases_[0] = (const char*)Ah; bases_[1] = (const char*)Al;                    \
            bases_[2] = (const char*)Bh; rb_ = (size_t)K * 2; ko_ = c_ * 64;             \
        } else {                                                                         \
            bases_[0] = (const char*)Th; bases_[1] = (const char*)Tl;                    \
            bases_[2] = (const char*)LUh; rb_ = 64; ko_ = 0;                             \
        }                                                                                \
        _Pragma("unroll")                                                                \
        for (int j = 0; j < 6; ++j) {                                                    \
            int i = tid + j * 256;                                                       \
            int mat = i >> 9, r = (i >> 2) & 127, seg = i & 3;                           \
            int gr = (mat < 2 ? bm : bn) + r;                                            \
            const char* s_ = bases_[mat] + (size_t)gr * rb_ + ko_ + seg * 16;            \
            cpa16(sb_ + mat * 10240 + r * 80 + seg * 16, s_);                            \
        }                                                                                \
        cpcommit();                                                                      \
    }

    LOAD_STAGE(0);
    for (int c = 0; c < TOT; ++c) {
        if (c + 1 < TOT) { LOAD_STAGE(c + 1); cpwait<1>(); }
        else { cpwait<0>(); }
        __syncthreads();
        unsigned sb = sbase + (c & 1) * STG_B;
#pragma unroll
        for (int s = 0; s < 2; ++s) {
            unsigned ahf[4][4], alf[4][4];
#pragma unroll
            for (int mf = 0; mf < 4; ++mf) {
                unsigned row = wm * 64 + mf * 16 + (lane & 15);
                unsigned off = row * 80 + s * 32 + ((lane >> 4) << 4);
                ldmx4(ahf[mf], sb + off);
                ldmx4(alf[mf], sb + 10240 + off);
            }
#pragma unroll
            for (int nf = 0; nf < 4; ++nf) {
                unsigned brow = wn * 32 + nf * 8 + (lane & 7);
                unsigned bh2[2];
                ldmx2(bh2, sb + 20480 + brow * 80 + s * 32 + (((lane >> 3) & 1) << 4));
#pragma unroll
                for (int mf = 0; mf < 4; ++mf) {
                    mmaH(acc[mf][nf], ahf[mf], bh2);
                    mmaH(acc[mf][nf], alf[mf], bh2);
                }
            }
        }
        __syncthreads();
    }

    // epilogue
#pragma unroll
    for (int nf = 0; nf < 4; ++nf) {
        int gn = bn + wn * 32 + nf * 8 + (lane & 3) * 2;
        float b0 = bias[gn], b1 = bias[gn + 1];
        float g0 = 0.f, g1 = 0.f;
        if (MODE == 1) { g0 = GATE[gn]; g1 = GATE[gn + 1]; }
#pragma unroll
        for (int mf = 0; mf < 4; ++mf) {
            int gm = bm + wm * 64 + mf * 16 + (lane >> 2);
            float v0 = acc[mf][nf][0] + b0, v1 = acc[mf][nf][1] + b1;
            float v2 = acc[mf][nf][2] + b0, v3 = acc[mf][nf][3] + b1;
            if (MODE == 2) { v0 = gelu2(v0); v1 = gelu2(v1); v2 = gelu2(v2); v3 = gelu2(v3); }
            if (MODE == 1) {
                float2 r0 = *(const float2*)&RES[(size_t)gm * N + gn];
                float2 r1 = *(const float2*)&RES[(size_t)(gm + 8) * N + gn];
                v0 = r0.x + g0 * v0; v1 = r0.y + g1 * v1;
                v2 = r1.x + g0 * v2; v3 = r1.y + g1 * v3;
            }
            *(float2*)&C[(size_t)gm * N + gn] = make_float2(v0, v1);
            *(float2*)&C[(size_t)(gm + 8) * N + gn] = make_float2(v2, v3);
            if (MODE == 2) {
                __half h0 = __float2half_rn(v0), h1 = __float2half_rn(v1);
                __half h2 = __float2half_rn(v2), h3 = __float2half_rn(v3);
                *(__half2*)&AoH[(size_t)gm * N + gn] = __halves2half2(h0, h1);
                *(__half2*)&AoL[(size_t)gm * N + gn] = __halves2half2(
                    __float2half_rn(v0 - __half2float(h0)), __float2half_rn(v1 - __half2float(h1)));
                *(__half2*)&AoH[(size_t)(gm + 8) * N + gn] = __halves2half2(h2, h3);
                *(__half2*)&AoL[(size_t)(gm + 8) * N + gn] = __halves2half2(
                    __float2half_rn(v2 - __half2float(h2)), __float2half_rn(v3 - __half2float(h3)));
            }
        }
    }
}

// ---------------- small kernels ----------------
__device__ __forceinline__ void blockReduce2(float& a, float& b, float* sbuf) {
    int lane = threadIdx.x & 31, w = threadIdx.x >> 5;
    int nw = blockDim.x >> 5;
#pragma unroll
    for (int o = 16; o; o >>= 1) {
        a += __shfl_xor_sync(0xffffffffu, a, o);
        b += __shfl_xor_sync(0xffffffffu, b, o);
    }
    if (lane == 0) { sbuf[w] = a; sbuf[nw + w] = b; }
    __syncthreads();
    a = 0.f; b = 0.f;
    for (int i = 0; i < nw; ++i) { a += sbuf[i]; b += sbuf[nw + i]; }
    __syncthreads();
}

__global__ void silu_kernel(const float* __restrict__ v, float* __restrict__ o) {
    int i = blockIdx.x * 256 + threadIdx.x;
    if (i < HID) { float x = v[i]; o[i] = x / (1.f + __expf(-x)); }
}

__global__ void __launch_bounds__(128) gemv_mod(const float* __restrict__ w,
                                                const float* __restrict__ b,
                                                const float* __restrict__ sv,
                                                float* __restrict__ o) {
    __shared__ float sbuf[8];
    int n = blockIdx.x;
    const float4* wr = (const float4*)(w + (size_t)n * HID);
    const float4* vv = (const float4*)sv;
    int t = threadIdx.x;
    float s = 0.f;
#pragma unroll
    for (int i = 0; i < 6; ++i) {
        float4 a = wr[t + i * 128], c = vv[t + i * 128];
        s += a.x * c.x + a.y * c.y + a.z * c.z + a.w * c.w;
    }
    float dummy = 0.f;
    blockReduce2(s, dummy, sbuf);
    if (t == 0) o[n] = s + b[n];
}

// LN + modulation; fp16 hi/lo outputs
__global__ void __launch_bounds__(256) ln_modH(const float* __restrict__ x,
                                               const float* __restrict__ sh,
                                               const float* __restrict__ sc,
                                               float* __restrict__ o,
                                               __half* __restrict__ dh,
                                               __half* __restrict__ dl) {
    __shared__ float sbuf[16];
    int row = blockIdx.x, t = threadIdx.x;
    const float4* xr = (const float4*)(x + (size_t)row * HID);
    float4 v[3];
    float s = 0.f, s2 = 0.f;
#pragma unroll
    for (int i = 0; i < 3; ++i) {
        v[i] = xr[t + i * 256];
        s += v[i].x + v[i].y + v[i].z + v[i].w;
        s2 += v[i].x * v[i].x + v[i].y * v[i].y + v[i].z * v[i].z + v[i].w * v[i].w;
    }
    blockReduce2(s, s2, sbuf);
    float mean = s * (1.f / HID);
    float var = s2 * (1.f / HID) - mean * mean;
    float rstd = rsqrtf(var + EPSF);
    float4* orow = (float4*)(o + (size_t)row * HID);
    uint2* hrow = (uint2*)(dh + (size_t)row * HID);
    uint2* lrow = (uint2*)(dl + (size_t)row * HID);
    const float4* sh4 = (const float4*)sh;
    const float4* sc4 = (const float4*)sc;
#pragma unroll
    for (int i = 0; i < 3; ++i) {
        int c = t + i * 256;
        float4 scv = sc4[c], shv = sh4[c], r;
        r.x = (v[i].x - mean) * rstd * (1.f + scv.x) + shv.x;
        r.y = (v[i].y - mean) * rstd * (1.f + scv.y) + shv.y;
        r.z = (v[i].z - mean) * rstd * (1.f + scv.z) + shv.z;
        r.w = (v[i].w - mean) * rstd * (1.f + scv.w) + shv.w;
        orow[c] = r;
        __half h[4], l[4];
        float rv[4] = {r.x, r.y, r.z, r.w};
#pragma unroll
        for (int j = 0; j < 4; ++j) {
            h[j] = __float2half_rn(rv[j]);
            l[j] = __float2half_rn(rv[j] - __half2float(h[j]));
        }
        hrow[c] = *(uint2*)h;
        lrow[c] = *(uint2*)l;
    }
}

__global__ void __launch_bounds__(256) tgemm2(const float* __restrict__ A,
                                              const float* __restrict__ LD,
                                              float* __restrict__ T, int K) {
    __shared__ float Ls[64 * 32];
    __shared__ float As[32 * 68];
    int tid = threadIdx.x, lane = tid & 31, w = tid >> 5;
    int bm = blockIdx.x * 32;
    float acc[4] = {0.f, 0.f, 0.f, 0.f};
    for (int k0 = 0; k0 < K; k0 += 64) {
        __syncthreads();
#pragma unroll
        for (int j = 0; j < 8; ++j) {
            int i = tid + j * 256;
            Ls[i] = LD[(size_t)(k0 + (i >> 5)) * 32 + (i & 31)];
        }
#pragma unroll
        for (int j = 0; j < 8; ++j) {
            int i = tid + j * 256;
            int r = i >> 6, c = i & 63;
            As[r * 68 + c] = A[(size_t)(bm + r) * K + k0 + c];
        }
        __syncthreads();
#pragma unroll 8
        for (int kk = 0; kk < 64; ++kk) {
            float ldv = Ls[kk * 32 + lane];
#pragma unroll
            for (int i = 0; i < 4; ++i) acc[i] += As[(w * 4 + i) * 68 + kk] * ldv;
        }
    }
#pragma unroll
    for (int i = 0; i < 4; ++i) T[(size_t)(bm + w * 4 + i) * 32 + lane] = acc[i];
}

__global__ void __launch_bounds__(64) rmsrope(const float* __restrict__ qkv,
                                              const float* __restrict__ wq,
                                              const float* __restrict__ wk,
                                              const float* __restrict__ pe, int loff,
                                              float* __restrict__ Q, float* __restrict__ K,
                                              float* __restrict__ V) {
    __shared__ float sbuf[4];
    int row = blockIdx.x, h = blockIdx.y, p = threadIdx.x;
    int l = loff + row;
    const float* base = qkv + (size_t)row * (3 * HID) + h * HD;
    float q0 = base[2 * p], q1 = base[2 * p + 1];
    float k0 = base[HID + 2 * p], k1 = base[HID + 2 * p + 1];
    float sq = q0 * q0 + q1 * q1, sk = k0 * k0 + k1 * k1;
#pragma unroll
    for (int o = 16; o; o >>= 1) {
        sq += __shfl_xor_sync(0xffffffffu, sq, o);
        sk += __shfl_xor_sync(0xffffffffu, sk, o);
    }
    int w = p >> 5;
    if ((p & 31) == 0) { sbuf[w] = sq; sbuf[2 + w] = sk; }
    __syncthreads();
    sq = sbuf[0] + sbuf[1];
    sk = sbuf[2] + sbuf[3];
    float rq = rsqrtf(sq * (1.f / HD) + EPSF);
    float rk = rsqrtf(sk * (1.f / HD) + EPSF);
    q0 *= rq * wq[2 * p]; q1 *= rq * wq[2 * p + 1];
    k0 *= rk * wk[2 * p]; k1 *= rk * wk[2 * p + 1];
    float4 f = ((const float4*)(pe + (size_t)l * 256))[p];
    size_t ob = (size_t)l * HID + h * HD;
    Q[ob + 2 * p] = f.x * q0 + f.y * q1;
    Q[ob + 2 * p + 1] = f.z * q0 + f.w * q1;
    K[ob + 2 * p] = f.x * k0 + f.y * k1;
    K[ob + 2 * p + 1] = f.z * k0 + f.w * k1;
    V[ob + 2 * p] = base[2 * HID + 2 * p];
    V[ob + 2 * p + 1] = base[2 * HID + 2 * p + 1];
}

#define FLASH_SMEM ((3 * 64 * 132 + 64 * 65) * 4)
__global__ void __launch_bounds__(256) flash(const float* __restrict__ Qg,
                                             const float* __restrict__ Kg,
                                             const float* __restrict__ Vg,
                                             float* __restrict__ Og,
                                             __half* __restrict__ Dh,
                                             __half* __restrict__ Dl) {
    extern __shared__ float smf[];
    float* Qs = smf;
    float* Ks = Qs + 64 * 132;
    float* Vs = Ks + 64 * 132;
    float* Ps = Vs + 64 * 132;
    int h = blockIdx.y;
    int qb = blockIdx.x * 64;
    int t = threadIdx.x, r = t >> 2, g = t & 3;
    const float scale = 0.08838834764831845f;

    for (int i = t; i < 64 * 32; i += 256) {
        int rr = i >> 5, c = i & 31;
        float4 qv = ((const float4*)(Qg + (size_t)(qb + rr) * HID + h * HD))[c];
        qv.x *= scale; qv.y *= scale; qv.z *= scale; qv.w *= scale;
        ((float4*)Qs)[rr * 33 + c] = qv;
    }
    float m = -1e30f, lsum = 0.f;
    float4 acc[8];
#pragma unroll
    for (int w = 0; w < 8; ++w) acc[w] = make_float4(0.f, 0.f, 0.f, 0.f);

    for (int kt = 0; kt < L_TOT; kt += 64) {
        __syncthreads();
        for (int i = t; i < 64 * 32; i += 256) {
            int rr = i >> 5, c = i & 31;
            ((float4*)Ks)[rr * 33 + c] = ((const float4*)(Kg + (size_t)(kt + rr) * HID + h * HD))[c];
            ((float4*)Vs)[rr * 33 + c] = ((const float4*)(Vg + (size_t)(kt + rr) * HID + h * HD))[c];
        }
        __syncthreads();

        float s[16];
#pragma unroll
        for (int jj = 0; jj < 16; ++jj) s[jj] = 0.f;
#pragma unroll 8
        for (int d4 = 0; d4 < 32; ++d4) {
            float4 qv = ((const float4*)Qs)[r * 33 + d4];
#pragma unroll
            for (int jj = 0; jj < 16; ++jj) {
                float4 kv = ((const float4*)Ks)[(g + 4 * jj) * 33 + d4];
                s[jj] += qv.x * kv.x + qv.y * kv.y + qv.z * kv.z + qv.w * kv.w;
            }
        }
        float tm = s[0];
#pragma unroll
        for (int jj = 1; jj < 16; ++jj) tm = fmaxf(tm, s[jj]);
        tm = fmaxf(tm, __shfl_xor_sync(0xffffffffu, tm, 1));
        tm = fmaxf(tm, __shfl_xor_sync(0xffffffffu, tm, 2));
        float mn = fmaxf(m, tm);
        float corr = __expf(m - mn);
        float ps = 0.f;
#pragma unroll
        for (int jj = 0; jj < 16; ++jj) {
            float pv = __expf(s[jj] - mn);
            Ps[r * 65 + g + 4 * jj] = pv;
            ps += pv;
        }
        ps += __shfl_xor_sync(0xffffffffu, ps, 1);
        ps += __shfl_xor_sync(0xffffffffu, ps, 2);
        lsum = lsum * corr + ps;
        m = mn;
#pragma unroll
        for (int w = 0; w < 8; ++w) {
            acc[w].x *= corr; acc[w].y *= corr; acc[w].z *= corr; acc[w].w *= corr;
        }
        __syncthreads();
#pragma unroll 4
        for (int j = 0; j < 64; ++j) {
            float pv = Ps[r * 65 + j];
#pragma unroll
            for (int w = 0; w < 8; ++w) {
                float4 vv = ((const float4*)Vs)[j * 33 + g + 4 * w];
                acc[w].x += pv * vv.x; acc[w].y += pv * vv.y;
                acc[w].z += pv * vv.z; acc[w].w += pv * vv.w;
            }
        }
    }
    float inv = 1.f / lsum;
    size_t orow = (size_t)(qb + r) * HID + h * HD;
#pragma unroll
    for (int w = 0; w < 8; ++w) {
        float4 o;
        o.x = acc[w].x * inv; o.y = acc[w].y * inv;
        o.z = acc[w].z * inv; o.w = acc[w].w * inv;
        ((float4*)(Og + orow))[g + 4 * w] = o;
        __half hh[4], ll[4];
        float ov[4] = {o.x, o.y, o.z, o.w};
#pragma unroll
        for (int j = 0; j < 4; ++j) {
            hh[j] = __float2half_rn(ov[j]);
            ll[j] = __float2half_rn(ov[j] - __half2float(hh[j]));
        }
        ((uint2*)(Dh + orow))[g + 4 * w] = *(uint2*)hh;
        ((uint2*)(Dl + orow))[g + 4 * w] = *(uint2*)ll;
    }
}

// ---------------- host ----------------
extern "C" void kernel_launch(void* const* d_in, const int* in_sizes, int n_in,
                              void* d_out, int out_size) {
    const float* img = (const float*)d_in[0];
    const float* txt = (const float*)d_in[1];
    const float* vec = (const float*)d_in[2];
    const float* pe = (const float*)d_in[3];
    const float* mod_w = (const float*)d_in[4];
    const float* mod_b = (const float*)d_in[5];
    const float* qkv_w = (const float*)d_in[6];
    const float* qkv_b = (const float*)d_in[7];
    const float* qkv_ld = (const float*)d_in[8];
    const float* qkv_lu = (const float*)d_in[9];
    const float* rmsq_w = (const float*)d_in[10];
    const float* rmsk_w = (const float*)d_in[11];
    const float* proj_w = (const float*)d_in[12];
    const float* proj_b = (const float*)d_in[13];
    const float* proj_ld = (const float*)d_in[14];
    const float* proj_lu = (const float*)d_in[15];
    const float* mlp0_w = (const float*)d_in[16];
    const float* mlp0_b = (const float*)d_in[17];
    const float* mlp0_ld = (const float*)d_in[18];
    const float* mlp0_lu = (const float*)d_in[19];
    const float* mlp2_w = (const float*)d_in[20];
    const float* mlp2_b = (const float*)d_in[21];
    const float* mlp2_ld = (const float*)d_in[22];
    const float* mlp2_lu = (const float*)d_in[23];
    float* out = (float*)d_out;

    float *sv, *mod, *xm, *tb, *qkv, *q, *k, *v, *attn, *x1, *hb;
    __half *wq16, *wp16, *w016, *w216, *a2h, *a2l, *f2h, *f2l, *b2h, *b2l, *t2h, *t2l, *lu2h;
    cudaGetSymbolAddress((void**)&sv, g_sv);
    cudaGetSymbolAddress((void**)&mod, g_mod);
    cudaGetSymbolAddress((void**)&xm, g_xm);
    cudaGetSymbolAddress((void**)&tb, g_t);
    cudaGetSymbolAddress((void**)&qkv, g_qkv);
    cudaGetSymbolAddress((void**)&q, g_q);
    cudaGetSymbolAddress((void**)&k, g_k);
    cudaGetSymbolAddress((void**)&v, g_v);
    cudaGetSymbolAddress((void**)&attn, g_attn);
    cudaGetSymbolAddress((void**)&x1, g_x1);
    cudaGetSymbolAddress((void**)&hb, g_h);
    cudaGetSymbolAddress((void**)&wq16, g_wq16);
    cudaGetSymbolAddress((void**)&wp16, g_wp16);
    cudaGetSymbolAddress((void**)&w016, g_w016);
    cudaGetSymbolAddress((void**)&w216, g_w216);
    cudaGetSymbolAddress((void**)&a2h, g_a2h);
    cudaGetSymbolAddress((void**)&a2l, g_a2l);
    cudaGetSymbolAddress((void**)&f2h, g_f2h);
    cudaGetSymbolAddress((void**)&f2l, g_f2l);
    cudaGetSymbolAddress((void**)&b2h, g_b2h);
    cudaGetSymbolAddress((void**)&b2l, g_b2l);
    cudaGetSymbolAddress((void**)&t2h, g_t2h);
    cudaGetSymbolAddress((void**)&t2l, g_t2l);
    cudaGetSymbolAddress((void**)&lu2h, g_lu2h);

    cudaFuncSetAttribute(flash, cudaFuncAttributeMaxDynamicSharedMemorySize, FLASH_SMEM);
    cudaFuncSetAttribute(gemm16<0>, cudaFuncAttributeMaxDynamicSharedMemorySize, GEMM_SMEM);
    cudaFuncSetAttribute(gemm16<1>, cudaFuncAttributeMaxDynamicSharedMemorySize, GEMM_SMEM);
    cudaFuncSetAttribute(gemm16<2>, cudaFuncAttributeMaxDynamicSharedMemorySize, GEMM_SMEM);

    silu_kernel<<<(HID + 255) / 256, 256>>>(vec, sv);
    gemv_mod<<<2 * 6 * HID, 128>>>(mod_w, mod_b, sv, mod);

    // weight conversions (fp16 single)
    convH16<<<(int)((2 * QKV_SZ / 4 + 255) / 256), 256>>>(qkv_w, wq16, 2 * QKV_SZ / 4);
    convH16<<<(int)((2 * PRJ_SZ / 4 + 255) / 256), 256>>>(proj_w, wp16, 2 * PRJ_SZ / 4);
    convH16<<<(int)((2 * MLP_SZ / 4 + 255) / 256), 256>>>(mlp0_w, w016, 2 * MLP_SZ / 4);
    convH16<<<(int)((2 * MLP_SZ / 4 + 255) / 256), 256>>>(mlp2_w, w216, 2 * MLP_SZ / 4);

    // pre(): s=0 img, s=1 txt
    for (int s = 0; s < 2; ++s) {
        const float* x = s == 0 ? img : txt;
        int M = s == 0 ? IMGL : TXTL;
        int loff = s == 0 ? TXTL : 0;
        const float* mm = mod + (size_t)s * 6 * HID;
        ln_modH<<<M, 256>>>(x, mm + 0 * HID, mm + 1 * HID, xm, a2h, a2l);
        tgemm2<<<M / 32, 256>>>(xm, qkv_ld + (size_t)s * HID * RANK, tb, HID);
        convHL16<<<(M * RANK / 4 + 255) / 256, 256>>>(tb, t2h, t2l, (size_t)M * RANK / 4);
        convLU16<<<(9216 * 32 + 255) / 256, 256>>>(qkv_lu + (size_t)s * RANK * 9216, lu2h, 9216);
        dim3 gq(M / 128, 9216 / 128);
        gemm16<0><<<gq, 256, GEMM_SMEM>>>(a2h, a2l, wq16 + s * QKV_SZ, t2h, t2l, lu2h,
                                          qkv_b + (size_t)s * 9216, nullptr, nullptr, qkv,
                                          nullptr, nullptr, M, 9216, HID);
        dim3 g2(M, HEADS);
        rmsrope<<<g2, 64>>>(qkv, rmsq_w + (size_t)s * HD, rmsk_w + (size_t)s * HD, pe, loff, q, k, v);
    }

    dim3 gf(L_TOT / 64, HEADS);
    flash<<<gf, 256, FLASH_SMEM>>>(q, k, v, attn, f2h, f2l);

    // post(): s=0 img (rows 512..), s=1 txt (rows 0..512)
    for (int s = 0; s < 2; ++s) {
        const float* x = s == 0 ? img : txt;
        int M = s == 0 ? IMGL : TXTL;
        int roff = s == 0 ? TXTL : 0;
        const float* a = attn + (size_t)roff * HID;
        const float* mm = mod + (size_t)s * 6 * HID;
        float* outp = out + (size_t)roff * HID;

        // x1 = x + g1 * svdq(a, proj)
        tgemm2<<<M / 32, 256>>>(a, proj_ld + (size_t)s * HID * RANK, tb, HID);
        convHL16<<<(M * RANK / 4 + 255) / 256, 256>>>(tb, t2h, t2l, (size_t)M * RANK / 4);
        convLU16<<<(HID * 32 + 255) / 256, 256>>>(proj_lu + (size_t)s * RANK * HID, lu2h, HID);
        dim3 gp(M / 128, HID / 128);
        gemm16<1><<<gp, 256, GEMM_SMEM>>>(f2h + (size_t)roff * HID, f2l + (size_t)roff * HID,
                                          wp16 + s * PRJ_SZ, t2h, t2l, lu2h,
                                          proj_b + (size_t)s * HID, x, mm + 2 * HID, x1,
                                          nullptr, nullptr, M, HID, HID);

        // h = gelu(svdq(ln_mod(x1), mlp0))
        ln_modH<<<M, 256>>>(x1, mm + 3 * HID, mm + 4 * HID, xm, a2h, a2l);
        tgemm2<<<M / 32, 256>>>(xm, mlp0_ld + (size_t)s * HID * RANK, tb, HID);
        convHL16<<<(M * RANK / 4 + 255) / 256, 256>>>(tb, t2h, t2l, (size_t)M * RANK / 4);
        convLU16<<<(MLPD * 32 + 255) / 256, 256>>>(mlp0_lu + (size_t)s * RANK * MLPD, lu2h, MLPD);
        dim3 gm0(M / 128, MLPD / 128);
        gemm16<2><<<gm0, 256, GEMM_SMEM>>>(a2h, a2l, w016 + s * MLP_SZ, t2h, t2l, lu2h,
                                           mlp0_b + (size_t)s * MLPD, nullptr, nullptr, hb,
                                           b2h, b2l, M, MLPD, HID);

        // out = x1 + g2 * svdq(h, mlp2)
        tgemm2<<<M / 32, 256>>>(hb, mlp2_ld + (size_t)s * MLPD * RANK, tb, MLPD);
        convHL16<<<(M * RANK / 4 + 255) / 256, 256>>>(tb, t2h, t2l, (size_t)M * RANK / 4);
        convLU16<<<(HID * 32 + 255) / 256, 256>>>(mlp2_lu + (size_t)s * RANK * HID, lu2h, HID);
        dim3 gm2(M / 128, HID / 128);
        gemm16<1><<<gm2, 256, GEMM_SMEM>>>(b2h, b2l, w216 + s * MLP_SZ, t2h, t2l, lu2h,
                                           mlp2_b + (size_t)s * HID, x1, mm + 5 * HID, outp,
                                           nullptr, nullptr, M, HID, MLPD);
    }
}

// round 11
// speedup vs baseline: 1.0020x; 1.0020x over previous
#include <cuda_runtime.h>
#include <cuda_bf16.h>
#include <cuda_fp16.h>
#include <math.h>

#define HID 3072
#define HEADS 24
#define HD 128
#define MLPD 12288
#define RANK 32
#define TXTL 512
#define IMGL 2048
#define L_TOT 2560
#define EPSF 1e-6f

#define QKV_SZ 28311552ULL
#define PRJ_SZ 9437184ULL
#define MLP_SZ 37748736ULL

// ---------------- device scratch ----------------
__device__ __align__(16) float g_sv[HID];
__device__ __align__(16) float g_mod[2 * 6 * HID];
__device__ __align__(16) float g_xm[(size_t)L_TOT * HID];
__device__ __align__(16) float g_t[(size_t)L_TOT * RANK];
__device__ __align__(16) float g_qkv[(size_t)L_TOT * 3 * HID];
__device__ __align__(16) float g_q[(size_t)L_TOT * HID];
__device__ __align__(16) float g_k[(size_t)L_TOT * HID];
__device__ __align__(16) float g_v[(size_t)L_TOT * HID];
__device__ __align__(16) float g_attn[(size_t)L_TOT * HID];
__device__ __align__(16) float g_x1[(size_t)L_TOT * HID];
__device__ __align__(16) float g_h[(size_t)IMGL * MLPD];

// fp16 weights (single, rounded)
__device__ __align__(16) __half g_wq16[2 * QKV_SZ];
__device__ __align__(16) __half g_wp16[2 * PRJ_SZ];
__device__ __align__(16) __half g_w016[2 * MLP_SZ];
__device__ __align__(16) __half g_w216[2 * MLP_SZ];
// fp16 activations (hi/lo)
__device__ __align__(16) __half g_a2h[(size_t)L_TOT * HID], g_a2l[(size_t)L_TOT * HID];
__device__ __align__(16) __half g_f2h[(size_t)L_TOT * HID], g_f2l[(size_t)L_TOT * HID];
__device__ __align__(16) __half g_b2h[(size_t)IMGL * MLPD], g_b2l[(size_t)IMGL * MLPD];
// lora
__device__ __align__(16) __half g_t2h[(size_t)L_TOT * RANK], g_t2l[(size_t)L_TOT * RANK];
__device__ __align__(16) __half g_lu2h[(size_t)MLPD * RANK];

// ---------------- asm helpers ----------------
__device__ __forceinline__ unsigned smem_u32(const void* p) {
    unsigned a;
    asm("{ .reg .u64 t; cvta.to.shared.u64 t, %1; cvt.u32.u64 %0, t; }" : "=r"(a) : "l"(p));
    return a;
}
__device__ __forceinline__ void ldmx4(unsigned (&r)[4], unsigned a) {
    asm volatile("ldmatrix.sync.aligned.m8n8.x4.shared.b16 {%0,%1,%2,%3}, [%4];"
                 : "=r"(r[0]), "=r"(r[1]), "=r"(r[2]), "=r"(r[3]) : "r"(a));
}
__device__ __forceinline__ void ldmx2(unsigned (&r)[2], unsigned a) {
    asm volatile("ldmatrix.sync.aligned.m8n8.x2.shared.b16 {%0,%1}, [%2];"
                 : "=r"(r[0]), "=r"(r[1]) : "r"(a));
}
__device__ __forceinline__ void mmaH(float (&d)[4], const unsigned (&a)[4], const unsigned (&b)[2]) {
    asm volatile("mma.sync.aligned.m16n8k16.row.col.f32.f16.f16.f32 "
                 "{%0,%1,%2,%3},{%4,%5,%6,%7},{%8,%9},{%0,%1,%2,%3};"
                 : "+f"(d[0]), "+f"(d[1]), "+f"(d[2]), "+f"(d[3])
                 : "r"(a[0]), "r"(a[1]), "r"(a[2]), "r"(a[3]), "r"(b[0]), "r"(b[1]));
}
__device__ __forceinline__ void cpa16(unsigned d, const void* s) {
    asm volatile("cp.async.cg.shared.global [%0], [%1], 16;" :: "r"(d), "l"(s));
}
__device__ __forceinline__ void cpcommit() { asm volatile("cp.async.commit_group;"); }
template <int N>
__device__ __forceinline__ void cpwait() { asm volatile("cp.async.wait_group %0;" :: "n"(N)); }

__device__ __forceinline__ float gelu2(float x) {
    float u = 0.7978845608028654f * (x + 0.044715f * x * x * x);
    float e = __expf(2.f * u);
    float th = 1.f - 2.f / (e + 1.f);
    return 0.5f * x * (1.f + th);
}

// ---------------- conversions ----------------
__global__ void __launch_bounds__(256) convH16(const float* __restrict__ src,
                                               __half* __restrict__ dh, size_t n4) {
    size_t idx = (size_t)blockIdx.x * 256 + threadIdx.x;
    if (idx >= n4) return;
    float4 v = ((const float4*)src)[idx];
    __half h[4] = {__float2half_rn(v.x), __float2half_rn(v.y),
                   __float2half_rn(v.z), __float2half_rn(v.w)};
    ((uint2*)dh)[idx] = *(uint2*)h;
}

__global__ void __launch_bounds__(256) convHL16(const float* __restrict__ src,
                                                __half* __restrict__ dh,
                                                __half* __restrict__ dl, size_t n4) {
    size_t idx = (size_t)blockIdx.x * 256 + threadIdx.x;
    if (idx >= n4) return;
    float4 v = ((const float4*)src)[idx];
    float vv[4] = {v.x, v.y, v.z, v.w};
    __half h[4], l[4];
#pragma unroll
    for (int i = 0; i < 4; ++i) {
        h[i] = __float2half_rn(vv[i]);
        l[i] = __float2half_rn(vv[i] - __half2float(h[i]));
    }
    ((uint2*)dh)[idx] = *(uint2*)h;
    ((uint2*)dl)[idx] = *(uint2*)l;
}

__global__ void __launch_bounds__(256) convLU16(const float* __restrict__ LU,
                                                __half* __restrict__ dh, int N) {
    int idx = blockIdx.x * 256 + threadIdx.x;
    if (idx >= N * 32) return;
    int n = idx >> 5, c = idx & 31;
    dh[(size_t)n * 32 + c] = __float2half_rn(LU[(size_t)c * N + n]);
}

// ---------------- fp16 2-pass split-precision GEMM ----------------
// stage (pitch 80B): Ah 0, Al 10240, Bh 20480 ; stage = 30720
#define STG_B 30720
#define GEMM_SMEM (2 * STG_B)

template <int MODE>
__global__ void __launch_bounds__(256, 2) gemm16(
    const __half* __restrict__ Ah, const __half* __restrict__ Al,
    const __half* __restrict__ Bh,
    const __half* __restrict__ Th, const __half* __restrict__ Tl,
    const __half* __restrict__ LUh,
    const float* __restrict__ bias, const float* __restrict__ RES,
    const float* __restrict__ GATE, float* __restrict__ C,
    __half* __restrict__ AoH, __half* __restrict__ AoL,
    int M, int N, int K) {
    extern __shared__ char sm[];
    unsigned sbase = smem_u32(sm);
    int tid = threadIdx.x, lane = tid & 31, wid = tid >> 5;
    int wm = wid >> 2, wn = wid & 3;
    int bm = blockIdx.x * 128, bn = blockIdx.y * 128;
    int KC = K >> 5, TOT = KC + 1;

    float acc[4][4][4];
#pragma unroll
    for (int a = 0; a < 4; ++a)
#pragma unroll
        for (int b = 0; b < 4; ++b)
#pragma unroll
            for (int c = 0; c < 4; ++c) acc[a][b][c] = 0.f;

#define LOAD_STAGE(cc)                                                                   \
    {                                                                                    \
        int c_ = (cc);                                                                   \
        unsigned sb_ = sbase + (c_ & 1) * STG_B;                                         \
        const char* bases_[3];                                                           \
        size_t rb_; int ko_;                                                             \
        if (c_ < KC) {                                                                   \
            bases_[0] = (const char*)Ah; bases_[1] = (const char*)Al;                    \
            bases_[2] = (const char*)Bh; rb_ = (size_t)K * 2; ko_ = c_ * 64;             \
        } else {                                                                         \
            bases_[0] = (const char*)Th; bases_[1] = (const char*)Tl;                    \
            bases_[2] = (const char*)LUh; rb_ = 64; ko_ = 0;                             \
        }                                                                                \
        _Pragma("unroll")                                                                \
        for (int j = 0; j < 6; ++j) {                                                    \
            int i = tid + j * 256;                                                       \
            int mat = i >> 9, r = (i >> 2) & 127, seg = i & 3;                           \
            int gr = (mat < 2 ? bm : bn) + r;                                            \
            const char* s_ = bases_[mat] + (size_t)gr * rb_ + ko_ + seg * 16;            \
            cpa16(sb_ + mat * 10240 + r * 80 + seg * 16, s_);                            \
        }                                                                                \
        cpcommit();                                                                      \
    }

    LOAD_STAGE(0);
    for (int c = 0; c < TOT; ++c) {
        if (c + 1 < TOT) { LOAD_STAGE(c + 1); cpwait<1>(); }
        else { cpwait<0>(); }
        __syncthreads();
        unsigned sb = sbase + (c & 1) * STG_B;
#pragma unroll
        for (int s = 0; s < 2; ++s) {
            unsigned ahf[4][4], alf[4][4];
#pragma unroll
            for (int mf = 0; mf < 4; ++mf) {
                unsigned row = wm * 64 + mf * 16 + (lane & 15);
                unsigned off = row * 80 + s * 32 + ((lane >> 4) << 4);
                ldmx4(ahf[mf], sb + off);
                ldmx4(alf[mf], sb + 10240 + off);
            }
#pragma unroll
            for (int nf = 0; nf < 4; ++nf) {
                unsigned brow = wn * 32 + nf * 8 + (lane & 7);
                unsigned bh2[2];
                ldmx2(bh2, sb + 20480 + brow * 80 + s * 32 + (((lane >> 3) & 1) << 4));
#pragma unroll
                for (int mf = 0; mf < 4; ++mf) {
                    mmaH(acc[mf][nf], ahf[mf], bh2);
                    mmaH(acc[mf][nf], alf[mf], bh2);
                }
            }
        }
        __syncthreads();
    }

    // epilogue
#pragma unroll
    for (int nf = 0; nf < 4; ++nf) {
        int gn = bn + wn * 32 + nf * 8 + (lane & 3) * 2;
        float b0 = bias[gn], b1 = bias[gn + 1];
        float g0 = 0.f, g1 = 0.f;
        if (MODE == 1) { g0 = GATE[gn]; g1 = GATE[gn + 1]; }
#pragma unroll
        for (int mf = 0; mf < 4; ++mf) {
            int gm = bm + wm * 64 + mf * 16 + (lane >> 2);
            float v0 = acc[mf][nf][0] + b0, v1 = acc[mf][nf][1] + b1;
            float v2 = acc[mf][nf][2] + b0, v3 = acc[mf][nf][3] + b1;
            if (MODE == 2) { v0 = gelu2(v0); v1 = gelu2(v1); v2 = gelu2(v2); v3 = gelu2(v3); }
            if (MODE == 1) {
                float2 r0 = *(const float2*)&RES[(size_t)gm * N + gn];
                float2 r1 = *(const float2*)&RES[(size_t)(gm + 8) * N + gn];
                v0 = r0.x + g0 * v0; v1 = r0.y + g1 * v1;
                v2 = r1.x + g0 * v2; v3 = r1.y + g1 * v3;
            }
            *(float2*)&C[(size_t)gm * N + gn] = make_float2(v0, v1);
            *(float2*)&C[(size_t)(gm + 8) * N + gn] = make_float2(v2, v3);
            if (MODE == 2) {
                __half h0 = __float2half_rn(v0), h1 = __float2half_rn(v1);
                __half h2 = __float2half_rn(v2), h3 = __float2half_rn(v3);
                *(__half2*)&AoH[(size_t)gm * N + gn] = __halves2half2(h0, h1);
                *(__half2*)&AoL[(size_t)gm * N + gn] = __halves2half2(
                    __float2half_rn(v0 - __half2float(h0)), __float2half_rn(v1 - __half2float(h1)));
                *(__half2*)&AoH[(size_t)(gm + 8) * N + gn] = __halves2half2(h2, h3);
                *(__half2*)&AoL[(size_t)(gm + 8) * N + gn] = __halves2half2(
                    __float2half_rn(v2 - __half2float(h2)), __float2half_rn(v3 - __half2float(h3)));
            }
        }
    }
}

// ---------------- small kernels ----------------
__device__ __forceinline__ void blockReduce2(float& a, float& b, float* sbuf) {
    int lane = threadIdx.x & 31, w = threadIdx.x >> 5;
    int nw = blockDim.x >> 5;
#pragma unroll
    for (int o = 16; o; o >>= 1) {
        a += __shfl_xor_sync(0xffffffffu, a, o);
        b += __shfl_xor_sync(0xffffffffu, b, o);
    }
    if (lane == 0) { sbuf[w] = a; sbuf[nw + w] = b; }
    __syncthreads();
    a = 0.f; b = 0.f;
    for (int i = 0; i < nw; ++i) { a += sbuf[i]; b += sbuf[nw + i]; }
    __syncthreads();
}

__global__ void silu_kernel(const float* __restrict__ v, float* __restrict__ o) {
    int i = blockIdx.x * 256 + threadIdx.x;
    if (i < HID) { float x = v[i]; o[i] = x / (1.f + __expf(-x)); }
}

__global__ void __launch_bounds__(128) gemv_mod(const float* __restrict__ w,
                                                const float* __restrict__ b,
                                                const float* __restrict__ sv,
                                                float* __restrict__ o) {
    __shared__ float sbuf[8];
    int n = blockIdx.x;
    const float4* wr = (const float4*)(w + (size_t)n * HID);
    const float4* vv = (const float4*)sv;
    int t = threadIdx.x;
    float s = 0.f;
#pragma unroll
    for (int i = 0; i < 6; ++i) {
        float4 a = wr[t + i * 128], c = vv[t + i * 128];
        s += a.x * c.x + a.y * c.y + a.z * c.z + a.w * c.w;
    }
    float dummy = 0.f;
    blockReduce2(s, dummy, sbuf);
    if (t == 0) o[n] = s + b[n];
}

// LN + modulation; fp16 hi/lo outputs
__global__ void __launch_bounds__(256) ln_modH(const float* __restrict__ x,
                                               const float* __restrict__ sh,
                                               const float* __restrict__ sc,
                                               float* __restrict__ o,
                                               __half* __restrict__ dh,
                                               __half* __restrict__ dl) {
    __shared__ float sbuf[16];
    int row = blockIdx.x, t = threadIdx.x;
    const float4* xr = (const float4*)(x + (size_t)row * HID);
    float4 v[3];
    float s = 0.f, s2 = 0.f;
#pragma unroll
    for (int i = 0; i < 3; ++i) {
        v[i] = xr[t + i * 256];
        s += v[i].x + v[i].y + v[i].z + v[i].w;
        s2 += v[i].x * v[i].x + v[i].y * v[i].y + v[i].z * v[i].z + v[i].w * v[i].w;
    }
    blockReduce2(s, s2, sbuf);
    float mean = s * (1.f / HID);
    float var = s2 * (1.f / HID) - mean * mean;
    float rstd = rsqrtf(var + EPSF);
    float4* orow = (float4*)(o + (size_t)row * HID);
    uint2* hrow = (uint2*)(dh + (size_t)row * HID);
    uint2* lrow = (uint2*)(dl + (size_t)row * HID);
    const float4* sh4 = (const float4*)sh;
    const float4* sc4 = (const float4*)sc;
#pragma unroll
    for (int i = 0; i < 3; ++i) {
        int c = t + i * 256;
        float4 scv = sc4[c], shv = sh4[c], r;
        r.x = (v[i].x - mean) * rstd * (1.f + scv.x) + shv.x;
        r.y = (v[i].y - mean) * rstd * (1.f + scv.y) + shv.y;
        r.z = (v[i].z - mean) * rstd * (1.f + scv.z) + shv.z;
        r.w = (v[i].w - mean) * rstd * (1.f + scv.w) + shv.w;
        orow[c] = r;
        __half h[4], l[4];
        float rv[4] = {r.x, r.y, r.z, r.w};
#pragma unroll
        for (int j = 0; j < 4; ++j) {
            h[j] = __float2half_rn(rv[j]);
            l[j] = __float2half_rn(rv[j] - __half2float(h[j]));
        }
        hrow[c] = *(uint2*)h;
        lrow[c] = *(uint2*)l;
    }
}

__global__ void __launch_bounds__(256) tgemm2(const float* __restrict__ A,
                                              const float* __restrict__ LD,
                                              float* __restrict__ T, int K) {
    __shared__ float Ls[64 * 32];
    __shared__ float As[32 * 68];
    int tid = threadIdx.x, lane = tid & 31, w = tid >> 5;
    int bm = blockIdx.x * 32;
    float acc[4] = {0.f, 0.f, 0.f, 0.f};
    for (int k0 = 0; k0 < K; k0 += 64) {
        __syncthreads();
#pragma unroll
        for (int j = 0; j < 8; ++j) {
            int i = tid + j * 256;
            Ls[i] = LD[(size_t)(k0 + (i >> 5)) * 32 + (i & 31)];
        }
#pragma unroll
        for (int j = 0; j < 8; ++j) {
            int i = tid + j * 256;
            int r = i >> 6, c = i & 63;
            As[r * 68 + c] = A[(size_t)(bm + r) * K + k0 + c];
        }
        __syncthreads();
#pragma unroll 8
        for (int kk = 0; kk < 64; ++kk) {
            float ldv = Ls[kk * 32 + lane];
#pragma unroll
            for (int i = 0; i < 4; ++i) acc[i] += As[(w * 4 + i) * 68 + kk] * ldv;
        }
    }
#pragma unroll
    for (int i = 0; i < 4; ++i) T[(size_t)(bm + w * 4 + i) * 32 + lane] = acc[i];
}

__global__ void __launch_bounds__(64) rmsrope(const float* __restrict__ qkv,
                                              const float* __restrict__ wq,
                                              const float* __restrict__ wk,
                                              const float* __restrict__ pe, int loff,
                                              float* __restrict__ Q, float* __restrict__ K,
                                              float* __restrict__ V) {
    __shared__ float sbuf[4];
    int row = blockIdx.x, h = blockIdx.y, p = threadIdx.x;
    int l = loff + row;
    const float* base = qkv + (size_t)row * (3 * HID) + h * HD;
    float q0 = base[2 * p], q1 = base[2 * p + 1];
    float k0 = base[HID + 2 * p], k1 = base[HID + 2 * p + 1];
    float sq = q0 * q0 + q1 * q1, sk = k0 * k0 + k1 * k1;
#pragma unroll
    for (int o = 16; o; o >>= 1) {
        sq += __shfl_xor_sync(0xffffffffu, sq, o);
        sk += __shfl_xor_sync(0xffffffffu, sk, o);
    }
    int w = p >> 5;
    if ((p & 31) == 0) { sbuf[w] = sq; sbuf[2 + w] = sk; }
    __syncthreads();
    sq = sbuf[0] + sbuf[1];
    sk = sbuf[2] + sbuf[3];
    float rq = rsqrtf(sq * (1.f / HD) + EPSF);
    float rk = rsqrtf(sk * (1.f / HD) + EPSF);
    q0 *= rq * wq[2 * p]; q1 *= rq * wq[2 * p + 1];
    k0 *= rk * wk[2 * p]; k1 *= rk * wk[2 * p + 1];
    float4 f = ((const float4*)(pe + (size_t)l * 256))[p];
    size_t ob = (size_t)l * HID + h * HD;
    Q[ob + 2 * p] = f.x * q0 + f.y * q1;
    Q[ob + 2 * p + 1] = f.z * q0 + f.w * q1;
    K[ob + 2 * p] = f.x * k0 + f.y * k1;
    K[ob + 2 * p + 1] = f.z * k0 + f.w * k1;
    V[ob + 2 * p] = base[2 * HID + 2 * p];
    V[ob + 2 * p + 1] = base[2 * HID + 2 * p + 1];
}

#define FLASH_SMEM ((3 * 64 * 132 + 64 * 65) * 4)
__global__ void __launch_bounds__(256) flash(const float* __restrict__ Qg,
                                             const float* __restrict__ Kg,
                                             const float* __restrict__ Vg,
                                             float* __restrict__ Og,
                                             __half* __restrict__ Dh,
                                             __half* __restrict__ Dl) {
    extern __shared__ float smf[];
    float* Qs = smf;
    float* Ks = Qs + 64 * 132;
    float* Vs = Ks + 64 * 132;
    float* Ps = Vs + 64 * 132;
    int h = blockIdx.y;
    int qb = blockIdx.x * 64;
    int t = threadIdx.x, r = t >> 2, g = t & 3;
    const float scale = 0.08838834764831845f;

    for (int i = t; i < 64 * 32; i += 256) {
        int rr = i >> 5, c = i & 31;
        float4 qv = ((const float4*)(Qg + (size_t)(qb + rr) * HID + h * HD))[c];
        qv.x *= scale; qv.y *= scale; qv.z *= scale; qv.w *= scale;
        ((float4*)Qs)[rr * 33 + c] = qv;
    }
    float m = -1e30f, lsum = 0.f;
    float4 acc[8];
#pragma unroll
    for (int w = 0; w < 8; ++w) acc[w] = make_float4(0.f, 0.f, 0.f, 0.f);

    for (int kt = 0; kt < L_TOT; kt += 64) {
        __syncthreads();
        for (int i = t; i < 64 * 32; i += 256) {
            int rr = i >> 5, c = i & 31;
            ((float4*)Ks)[rr * 33 + c] = ((const float4*)(Kg + (size_t)(kt + rr) * HID + h * HD))[c];
            ((float4*)Vs)[rr * 33 + c] = ((const float4*)(Vg + (size_t)(kt + rr) * HID + h * HD))[c];
        }
        __syncthreads();

        float s[16];
#pragma unroll
        for (int jj = 0; jj < 16; ++jj) s[jj] = 0.f;
#pragma unroll 8
        for (int d4 = 0; d4 < 32; ++d4) {
            float4 qv = ((const float4*)Qs)[r * 33 + d4];
#pragma unroll
            for (int jj = 0; jj < 16; ++jj) {
                float4 kv = ((const float4*)Ks)[(g + 4 * jj) * 33 + d4];
                s[jj] += qv.x * kv.x + qv.y * kv.y + qv.z * kv.z + qv.w * kv.w;
            }
        }
        float tm = s[0];
#pragma unroll
        for (int jj = 1; jj < 16; ++jj) tm = fmaxf(tm, s[jj]);
        tm = fmaxf(tm, __shfl_xor_sync(0xffffffffu, tm, 1));
        tm = fmaxf(tm, __shfl_xor_sync(0xffffffffu, tm, 2));
        float mn = fmaxf(m, tm);
        float corr = __expf(m - mn);
        float ps = 0.f;
#pragma unroll
        for (int jj = 0; jj < 16; ++jj) {
            float pv = __expf(s[jj] - mn);
            Ps[r * 65 + g + 4 * jj] = pv;
            ps += pv;
        }
        ps += __shfl_xor_sync(0xffffffffu, ps, 1);
        ps += __shfl_xor_sync(0xffffffffu, ps, 2);
        lsum = lsum * corr + ps;
        m = mn;
#pragma unroll
        for (int w = 0; w < 8; ++w) {
            acc[w].x *= corr; acc[w].y *= corr; acc[w].z *= corr; acc[w].w *= corr;
        }
        __syncthreads();
#pragma unroll 4
        for (int j = 0; j < 64; ++j) {
            float pv = Ps[r * 65 + j];
#pragma unroll
            for (int w = 0; w < 8; ++w) {
                float4 vv = ((const float4*)Vs)[j * 33 + g + 4 * w];
                acc[w].x += pv * vv.x; acc[w].y += pv * vv.y;
                acc[w].z += pv * vv.z; acc[w].w += pv * vv.w;
            }
        }
    }
    float inv = 1.f / lsum;
    size_t orow = (size_t)(qb + r) * HID + h * HD;
#pragma unroll
    for (int w = 0; w < 8; ++w) {
        float4 o;
        o.x = acc[w].x * inv; o.y = acc[w].y * inv;
        o.z = acc[w].z * inv; o.w = acc[w].w * inv;
        ((float4*)(Og + orow))[g + 4 * w] = o;
        __half hh[4], ll[4];
        float ov[4] = {o.x, o.y, o.z, o.w};
#pragma unroll
        for (int j = 0; j < 4; ++j) {
            hh[j] = __float2half_rn(ov[j]);
            ll[j] = __float2half_rn(ov[j] - __half2float(hh[j]));
        }
        ((uint2*)(Dh + orow))[g + 4 * w] = *(uint2*)hh;
        ((uint2*)(Dl + orow))[g + 4 * w] = *(uint2*)ll;
    }
}

// ---------------- host ----------------
extern "C" void kernel_launch(void* const* d_in, const int* in_sizes, int n_in,
                              void* d_out, int out_size) {
    const float* img = (const float*)d_in[0];
    const float* txt = (const float*)d_in[1];
    const float* vec = (const float*)d_in[2];
    const float* pe = (const float*)d_in[3];
    const float* mod_w = (const float*)d_in[4];
    const float* mod_b = (const float*)d_in[5];
    const float* qkv_w = (const float*)d_in[6];
    const float* qkv_b = (const float*)d_in[7];
    const float* qkv_ld = (const float*)d_in[8];
    const float* qkv_lu = (const float*)d_in[9];
    const float* rmsq_w = (const float*)d_in[10];
    const float* rmsk_w = (const float*)d_in[11];
    const float* proj_w = (const float*)d_in[12];
    const float* proj_b = (const float*)d_in[13];
    const float* proj_ld = (const float*)d_in[14];
    const float* proj_lu = (const float*)d_in[15];
    const float* mlp0_w = (const float*)d_in[16];
    const float* mlp0_b = (const float*)d_in[17];
    const float* mlp0_ld = (const float*)d_in[18];
    const float* mlp0_lu = (const float*)d_in[19];
    const float* mlp2_w = (const float*)d_in[20];
    const float* mlp2_b = (const float*)d_in[21];
    const float* mlp2_ld = (const float*)d_in[22];
    const float* mlp2_lu = (const float*)d_in[23];
    float* out = (float*)d_out;

    float *sv, *mod, *xm, *tb, *qkv, *q, *k, *v, *attn, *x1, *hb;
    __half *wq16, *wp16, *w016, *w216, *a2h, *a2l, *f2h, *f2l, *b2h, *b2l, *t2h, *t2l, *lu2h;
    cudaGetSymbolAddress((void**)&sv, g_sv);
    cudaGetSymbolAddress((void**)&mod, g_mod);
    cudaGetSymbolAddress((void**)&xm, g_xm);
    cudaGetSymbolAddress((void**)&tb, g_t);
    cudaGetSymbolAddress((void**)&qkv, g_qkv);
    cudaGetSymbolAddress((void**)&q, g_q);
    cudaGetSymbolAddress((void**)&k, g_k);
    cudaGetSymbolAddress((void**)&v, g_v);
    cudaGetSymbolAddress((void**)&attn, g_attn);
    cudaGetSymbolAddress((void**)&x1, g_x1);
    cudaGetSymbolAddress((void**)&hb, g_h);
    cudaGetSymbolAddress((void**)&wq16, g_wq16);
    cudaGetSymbolAddress((void**)&wp16, g_wp16);
    cudaGetSymbolAddress((void**)&w016, g_w016);
    cudaGetSymbolAddress((void**)&w216, g_w216);
    cudaGetSymbolAddress((void**)&a2h, g_a2h);
    cudaGetSymbolAddress((void**)&a2l, g_a2l);
    cudaGetSymbolAddress((void**)&f2h, g_f2h);
    cudaGetSymbolAddress((void**)&f2l, g_f2l);
    cudaGetSymbolAddress((void**)&b2h, g_b2h);
    cudaGetSymbolAddress((void**)&b2l, g_b2l);
    cudaGetSymbolAddress((void**)&t2h, g_t2h);
    cudaGetSymbolAddress((void**)&t2l, g_t2l);
    cudaGetSymbolAddress((void**)&lu2h, g_lu2h);

    cudaFuncSetAttribute(flash, cudaFuncAttributeMaxDynamicSharedMemorySize, FLASH_SMEM);
    cudaFuncSetAttribute(gemm16<0>, cudaFuncAttributeMaxDynamicSharedMemorySize, GEMM_SMEM);
    cudaFuncSetAttribute(gemm16<1>, cudaFuncAttributeMaxDynamicSharedMemorySize, GEMM_SMEM);
    cudaFuncSetAttribute(gemm16<2>, cudaFuncAttributeMaxDynamicSharedMemorySize, GEMM_SMEM);

    silu_kernel<<<(HID + 255) / 256, 256>>>(vec, sv);
    gemv_mod<<<2 * 6 * HID, 128>>>(mod_w, mod_b, sv, mod);

    // weight conversions (fp16 single)
    convH16<<<(int)((2 * QKV_SZ / 4 + 255) / 256), 256>>>(qkv_w, wq16, 2 * QKV_SZ / 4);
    convH16<<<(int)((2 * PRJ_SZ / 4 + 255) / 256), 256>>>(proj_w, wp16, 2 * PRJ_SZ / 4);
    convH16<<<(int)((2 * MLP_SZ / 4 + 255) / 256), 256>>>(mlp0_w, w016, 2 * MLP_SZ / 4);
    convH16<<<(int)((2 * MLP_SZ / 4 + 255) / 256), 256>>>(mlp2_w, w216, 2 * MLP_SZ / 4);

    // pre(): s=0 img, s=1 txt
    for (int s = 0; s < 2; ++s) {
        const float* x = s == 0 ? img : txt;
        int M = s == 0 ? IMGL : TXTL;
        int loff = s == 0 ? TXTL : 0;
        const float* mm = mod + (size_t)s * 6 * HID;
        ln_modH<<<M, 256>>>(x, mm + 0 * HID, mm + 1 * HID, xm, a2h, a2l);
        tgemm2<<<M / 32, 256>>>(xm, qkv_ld + (size_t)s * HID * RANK, tb, HID);
        convHL16<<<(M * RANK / 4 + 255) / 256, 256>>>(tb, t2h, t2l, (size_t)M * RANK / 4);
        convLU16<<<(9216 * 32 + 255) / 256, 256>>>(qkv_lu + (size_t)s * RANK * 9216, lu2h, 9216);
        dim3 gq(M / 128, 9216 / 128);
        gemm16<0><<<gq, 256, GEMM_SMEM>>>(a2h, a2l, wq16 + s * QKV_SZ, t2h, t2l, lu2h,
                                          qkv_b + (size_t)s * 9216, nullptr, nullptr, qkv,
                                          nullptr, nullptr, M, 9216, HID);
        dim3 g2(M, HEADS);
        rmsrope<<<g2, 64>>>(qkv, rmsq_w + (size_t)s * HD, rmsk_w + (size_t)s * HD, pe, loff, q, k, v);
    }

    dim3 gf(L_TOT / 64, HEADS);
    flash<<<gf, 256, FLASH_SMEM>>>(q, k, v, attn, f2h, f2l);

    // post(): s=0 img (rows 512..), s=1 txt (rows 0..512)
    for (int s = 0; s < 2; ++s) {
        const float* x = s == 0 ? img : txt;
        int M = s == 0 ? IMGL : TXTL;
        int roff = s == 0 ? TXTL : 0;
        const float* a = attn + (size_t)roff * HID;
        const float* mm = mod + (size_t)s * 6 * HID;
        float* outp = out + (size_t)roff * HID;

        // x1 = x + g1 * svdq(a, proj)
        tgemm2<<<M / 32, 256>>>(a, proj_ld + (size_t)s * HID * RANK, tb, HID);
        convHL16<<<(M * RANK / 4 + 255) / 256, 256>>>(tb, t2h, t2l, (size_t)M * RANK / 4);
        convLU16<<<(HID * 32 + 255) / 256, 256>>>(proj_lu + (size_t)s * RANK * HID, lu2h, HID);
        dim3 gp(M / 128, HID / 128);
        gemm16<1><<<gp, 256, GEMM_SMEM>>>(f2h + (size_t)roff * HID, f2l + (size_t)roff * HID,
                                          wp16 + s * PRJ_SZ, t2h, t2l, lu2h,
                                          proj_b + (size_t)s * HID, x, mm + 2 * HID, x1,
                                          nullptr, nullptr, M, HID, HID);

        // h = gelu(svdq(ln_mod(x1), mlp0))
        ln_modH<<<M, 256>>>(x1, mm + 3 * HID, mm + 4 * HID, xm, a2h, a2l);
        tgemm2<<<M / 32, 256>>>(xm, mlp0_ld + (size_t)s * HID * RANK, tb, HID);
        convHL16<<<(M * RANK / 4 + 255) / 256, 256>>>(tb, t2h, t2l, (size_t)M * RANK / 4);
        convLU16<<<(MLPD * 32 + 255) / 256, 256>>>(mlp0_lu + (size_t)s * RANK * MLPD, lu2h, MLPD);
        dim3 gm0(M / 128, MLPD / 128);
        gemm16<2><<<gm0, 256, GEMM_SMEM>>>(a2h, a2l, w016 + s * MLP_SZ, t2h, t2l, lu2h,
                                           mlp0_b + (size_t)s * MLPD, nullptr, nullptr, hb,
                                           b2h, b2l, M, MLPD, HID);

        // out = x1 + g2 * svdq(h, mlp2)
        tgemm2<<<M / 32, 256>>>(hb, mlp2_ld + (size_t)s * MLPD * RANK, tb, MLPD);
        convHL16<<<(M * RANK / 4 + 255) / 256, 256>>>(tb, t2h, t2l, (size_t)M * RANK / 4);
        convLU16<<<(HID * 32 + 255) / 256, 256>>>(mlp2_lu + (size_t)s * RANK * HID, lu2h, HID);
        dim3 gm2(M / 128, HID / 128);
        gemm16<1><<<gm2, 256, GEMM_SMEM>>>(b2h, b2l, w216 + s * MLP_SZ, t2h, t2l, lu2h,
                                           mlp2_b + (size_t)s * HID, x1, mm + 5 * HID, outp,
                                           nullptr, nullptr, M, HID, MLPD);
    }
}

// round 12
// speedup vs baseline: 1.0022x; 1.0002x over previous
#include <cuda_runtime.h>
#include <cuda_bf16.h>
#include <cuda_fp16.h>
#include <math.h>

#define HID 3072
#define HEADS 24
#define HD 128
#define MLPD 12288
#define RANK 32
#define TXTL 512
#define IMGL 2048
#define L_TOT 2560
#define EPSF 1e-6f

#define QKV_SZ 28311552ULL
#define PRJ_SZ 9437184ULL
#define MLP_SZ 37748736ULL

// ---------------- device scratch ----------------
__device__ __align__(16) float g_sv[HID];
__device__ __align__(16) float g_mod[2 * 6 * HID];
__device__ __align__(16) float g_xm[(size_t)L_TOT * HID];
__device__ __align__(16) float g_t[(size_t)L_TOT * RANK];
__device__ __align__(16) float g_qkv[(size_t)L_TOT * 3 * HID];
__device__ __align__(16) float g_q[(size_t)L_TOT * HID];
__device__ __align__(16) float g_k[(size_t)L_TOT * HID];
__device__ __align__(16) float g_v[(size_t)L_TOT * HID];
__device__ __align__(16) float g_attn[(size_t)L_TOT * HID];
__device__ __align__(16) float g_x1[(size_t)L_TOT * HID];
__device__ __align__(16) float g_h[(size_t)IMGL * MLPD];

// fp16 weights (single, rounded)
__device__ __align__(16) __half g_wq16[2 * QKV_SZ];
__device__ __align__(16) __half g_wp16[2 * PRJ_SZ];
__device__ __align__(16) __half g_w016[2 * MLP_SZ];
__device__ __align__(16) __half g_w216[2 * MLP_SZ];
// fp16 activations (hi/lo)
__device__ __align__(16) __half g_a2h[(size_t)L_TOT * HID], g_a2l[(size_t)L_TOT * HID];
__device__ __align__(16) __half g_f2h[(size_t)L_TOT * HID], g_f2l[(size_t)L_TOT * HID];
__device__ __align__(16) __half g_b2h[(size_t)IMGL * MLPD], g_b2l[(size_t)IMGL * MLPD];
// lora
__device__ __align__(16) __half g_t2h[(size_t)L_TOT * RANK], g_t2l[(size_t)L_TOT * RANK];
__device__ __align__(16) __half g_lu2h[(size_t)MLPD * RANK];

// ---------------- asm helpers ----------------
__device__ __forceinline__ unsigned smem_u32(const void* p) {
    unsigned a;
    asm("{ .reg .u64 t; cvta.to.shared.u64 t, %1; cvt.u32.u64 %0, t; }" : "=r"(a) : "l"(p));
    return a;
}
__device__ __forceinline__ void ldmx4(unsigned (&r)[4], unsigned a) {
    asm volatile("ldmatrix.sync.aligned.m8n8.x4.shared.b16 {%0,%1,%2,%3}, [%4];"
                 : "=r"(r[0]), "=r"(r[1]), "=r"(r[2]), "=r"(r[3]) : "r"(a));
}
__device__ __forceinline__ void ldmx2(unsigned (&r)[2], unsigned a) {
    asm volatile("ldmatrix.sync.aligned.m8n8.x2.shared.b16 {%0,%1}, [%2];"
                 : "=r"(r[0]), "=r"(r[1]) : "r"(a));
}
__device__ __forceinline__ void mmaH(float (&d)[4], const unsigned (&a)[4], const unsigned (&b)[2]) {
    asm volatile("mma.sync.aligned.m16n8k16.row.col.f32.f16.f16.f32 "
                 "{%0,%1,%2,%3},{%4,%5,%6,%7},{%8,%9},{%0,%1,%2,%3};"
                 : "+f"(d[0]), "+f"(d[1]), "+f"(d[2]), "+f"(d[3])
                 : "r"(a[0]), "r"(a[1]), "r"(a[2]), "r"(a[3]), "r"(b[0]), "r"(b[1]));
}
__device__ __forceinline__ void cpa16(unsigned d, const void* s) {
    asm volatile("cp.async.cg.shared.global [%0], [%1], 16;" :: "r"(d), "l"(s));
}
__device__ __forceinline__ void cpcommit() { asm volatile("cp.async.commit_group;"); }
template <int N>
__device__ __forceinline__ void cpwait() { asm volatile("cp.async.wait_group %0;" :: "n"(N)); }

__device__ __forceinline__ float gelu2(float x) {
    float u = 0.7978845608028654f * (x + 0.044715f * x * x * x);
    float e = __expf(2.f * u);
    float th = 1.f - 2.f / (e + 1.f);
    return 0.5f * x * (1.f + th);
}

// ---------------- conversions ----------------
__global__ void __launch_bounds__(256) convH16(const float* __restrict__ src,
                                               __half* __restrict__ dh, size_t n4) {
    size_t idx = (size_t)blockIdx.x * 256 + threadIdx.x;
    if (idx >= n4) return;
    float4 v = ((const float4*)src)[idx];
    __half h[4] = {__float2half_rn(v.x), __float2half_rn(v.y),
                   __float2half_rn(v.z), __float2half_rn(v.w)};
    ((uint2*)dh)[idx] = *(uint2*)h;
}

__global__ void __launch_bounds__(256) convHL16(const float* __restrict__ src,
                                                __half* __restrict__ dh,
                                                __half* __restrict__ dl, size_t n4) {
    size_t idx = (size_t)blockIdx.x * 256 + threadIdx.x;
    if (idx >= n4) return;
    float4 v = ((const float4*)src)[idx];
    float vv[4] = {v.x, v.y, v.z, v.w};
    __half h[4], l[4];
#pragma unroll
    for (int i = 0; i < 4; ++i) {
        h[i] = __float2half_rn(vv[i]);
        l[i] = __float2half_rn(vv[i] - __half2float(h[i]));
    }
    ((uint2*)dh)[idx] = *(uint2*)h;
    ((uint2*)dl)[idx] = *(uint2*)l;
}

__global__ void __launch_bounds__(256) convLU16(const float* __restrict__ LU,
                                                __half* __restrict__ dh, int N) {
    int idx = blockIdx.x * 256 + threadIdx.x;
    if (idx >= N * 32) return;
    int n = idx >> 5, c = idx & 31;
    dh[(size_t)n * 32 + c] = __float2half_rn(LU[(size_t)c * N + n]);
}

// ---------------- fp16 2-pass split-precision GEMM ----------------
// stage (pitch 80B): Ah 0, Al 10240, Bh 20480 ; stage = 30720
#define STG_B 30720
#define GEMM_SMEM (2 * STG_B)

template <int MODE>
__global__ void __launch_bounds__(256, 2) gemm16(
    const __half* __restrict__ Ah, const __half* __restrict__ Al,
    const __half* __restrict__ Bh,
    const __half* __restrict__ Th, const __half* __restrict__ Tl,
    const __half* __restrict__ LUh,
    const float* __restrict__ bias, const float* __restrict__ RES,
    const float* __restrict__ GATE, float* __restrict__ C,
    __half* __restrict__ AoH, __half* __restrict__ AoL,
    int M, int N, int K) {
    extern __shared__ char sm[];
    unsigned sbase = smem_u32(sm);
    int tid = threadIdx.x, lane = tid & 31, wid = tid >> 5;
    int wm = wid >> 2, wn = wid & 3;
    int bm = blockIdx.x * 128, bn = blockIdx.y * 128;
    int KC = K >> 5, TOT = KC + 1;

    float acc[4][4][4];
#pragma unroll
    for (int a = 0; a < 4; ++a)
#pragma unroll
        for (int b = 0; b < 4; ++b)
#pragma unroll
            for (int c = 0; c < 4; ++c) acc[a][b][c] = 0.f;

#define LOAD_STAGE(cc)                                                                   \
    {                                                                                    \
        int c_ = (cc);                                                                   \
        unsigned sb_ = sbase + (c_ & 1) * STG_B;                                         \
        const char* bases_[3];                                                           \
        size_t rb_; int ko_;                                                             \
        if (c_ < KC) {                                                                   \
            bases_[0] = (const char*)Ah; bases_[1] = (const char*)Al;                    \
            bases_[2] = (const char*)Bh; rb_ = (size_t)K * 2; ko_ = c_ * 64;             \
        } else {                                                                         \
            bases_[0] = (const char*)Th; bases_[1] = (const char*)Tl;                    \
            bases_[2] = (const char*)LUh; rb_ = 64; ko_ = 0;                             \
        }                                                                                \
        _Pragma("unroll")                                                                \
        for (int j = 0; j < 6; ++j) {                                                    \
            int i = tid + j * 256;                                                       \
            int mat = i >> 9, r = (i >> 2) & 127, seg = i & 3;                           \
            int gr = (mat < 2 ? bm : bn) + r;                                            \
            const char* s_ = bases_[mat] + (size_t)gr * rb_ + ko_ + seg * 16;            \
            cpa16(sb_ + mat * 10240 + r * 80 + seg * 16, s_);                            \
        }                                                                                \
        cpcommit();                                                                      \
    }

    LOAD_STAGE(0);
    for (int c = 0; c < TOT; ++c) {
        if (c + 1 < TOT) { LOAD_STAGE(c + 1); cpwait<1>(); }
        else { cpwait<0>(); }
        __syncthreads();
        unsigned sb = sbase + (c & 1) * STG_B;
#pragma unroll
        for (int s = 0; s < 2; ++s) {
            unsigned ahf[4][4], alf[4][4];
#pragma unroll
            for (int mf = 0; mf < 4; ++mf) {
                unsigned row = wm * 64 + mf * 16 + (lane & 15);
                unsigned off = row * 80 + s * 32 + ((lane >> 4) << 4);
                ldmx4(ahf[mf], sb + off);
                ldmx4(alf[mf], sb + 10240 + off);
            }
#pragma unroll
            for (int nf = 0; nf < 4; ++nf) {
                unsigned brow = wn * 32 + nf * 8 + (lane & 7);
                unsigned bh2[2];
                ldmx2(bh2, sb + 20480 + brow * 80 + s * 32 + (((lane >> 3) & 1) << 4));
#pragma unroll
                for (int mf = 0; mf < 4; ++mf) {
                    mmaH(acc[mf][nf], ahf[mf], bh2);
                    mmaH(acc[mf][nf], alf[mf], bh2);
                }
            }
        }
        __syncthreads();
    }

    // epilogue
#pragma unroll
    for (int nf = 0; nf < 4; ++nf) {
        int gn = bn + wn * 32 + nf * 8 + (lane & 3) * 2;
        float b0 = bias[gn], b1 = bias[gn + 1];
        float g0 = 0.f, g1 = 0.f;
        if (MODE == 1) { g0 = GATE[gn]; g1 = GATE[gn + 1]; }
#pragma unroll
        for (int mf = 0; mf < 4; ++mf) {
            int gm = bm + wm * 64 + mf * 16 + (lane >> 2);
            float v0 = acc[mf][nf][0] + b0, v1 = acc[mf][nf][1] + b1;
            float v2 = acc[mf][nf][2] + b0, v3 = acc[mf][nf][3] + b1;
            if (MODE == 2) { v0 = gelu2(v0); v1 = gelu2(v1); v2 = gelu2(v2); v3 = gelu2(v3); }
            if (MODE == 1) {
                float2 r0 = *(const float2*)&RES[(size_t)gm * N + gn];
                float2 r1 = *(const float2*)&RES[(size_t)(gm + 8) * N + gn];
                v0 = r0.x + g0 * v0; v1 = r0.y + g1 * v1;
                v2 = r1.x + g0 * v2; v3 = r1.y + g1 * v3;
            }
            *(float2*)&C[(size_t)gm * N + gn] = make_float2(v0, v1);
            *(float2*)&C[(size_t)(gm + 8) * N + gn] = make_float2(v2, v3);
            if (MODE == 2) {
                __half h0 = __float2half_rn(v0), h1 = __float2half_rn(v1);
                __half h2 = __float2half_rn(v2), h3 = __float2half_rn(v3);
                *(__half2*)&AoH[(size_t)gm * N + gn] = __halves2half2(h0, h1);
                *(__half2*)&AoL[(size_t)gm * N + gn] = __halves2half2(
                    __float2half_rn(v0 - __half2float(h0)), __float2half_rn(v1 - __half2float(h1)));
                *(__half2*)&AoH[(size_t)(gm + 8) * N + gn] = __halves2half2(h2, h3);
                *(__half2*)&AoL[(size_t)(gm + 8) * N + gn] = __halves2half2(
                    __float2half_rn(v2 - __half2float(h2)), __float2half_rn(v3 - __half2float(h3)));
            }
        }
    }
}

// ---------------- small kernels ----------------
__device__ __forceinline__ void blockReduce2(float& a, float& b, float* sbuf) {
    int lane = threadIdx.x & 31, w = threadIdx.x >> 5;
    int nw = blockDim.x >> 5;
#pragma unroll
    for (int o = 16; o; o >>= 1) {
        a += __shfl_xor_sync(0xffffffffu, a, o);
        b += __shfl_xor_sync(0xffffffffu, b, o);
    }
    if (lane == 0) { sbuf[w] = a; sbuf[nw + w] = b; }
    __syncthreads();
    a = 0.f; b = 0.f;
    for (int i = 0; i < nw; ++i) { a += sbuf[i]; b += sbuf[nw + i]; }
    __syncthreads();
}

__global__ void silu_kernel(const float* __restrict__ v, float* __restrict__ o) {
    int i = blockIdx.x * 256 + threadIdx.x;
    if (i < HID) { float x = v[i]; o[i] = x / (1.f + __expf(-x)); }
}

__global__ void __launch_bounds__(128) gemv_mod(const float* __restrict__ w,
                                                const float* __restrict__ b,
                                                const float* __restrict__ sv,
                                                float* __restrict__ o) {
    __shared__ float sbuf[8];
    int n = blockIdx.x;
    const float4* wr = (const float4*)(w + (size_t)n * HID);
    const float4* vv = (const float4*)sv;
    int t = threadIdx.x;
    float s = 0.f;
#pragma unroll
    for (int i = 0; i < 6; ++i) {
        float4 a = wr[t + i * 128], c = vv[t + i * 128];
        s += a.x * c.x + a.y * c.y + a.z * c.z + a.w * c.w;
    }
    float dummy = 0.f;
    blockReduce2(s, dummy, sbuf);
    if (t == 0) o[n] = s + b[n];
}

// LN + modulation; fp16 hi/lo outputs
__global__ void __launch_bounds__(256) ln_modH(const float* __restrict__ x,
                                               const float* __restrict__ sh,
                                               const float* __restrict__ sc,
                                               float* __restrict__ o,
                                               __half* __restrict__ dh,
                                               __half* __restrict__ dl) {
    __shared__ float sbuf[16];
    int row = blockIdx.x, t = threadIdx.x;
    const float4* xr = (const float4*)(x + (size_t)row * HID);
    float4 v[3];
    float s = 0.f, s2 = 0.f;
#pragma unroll
    for (int i = 0; i < 3; ++i) {
        v[i] = xr[t + i * 256];
        s += v[i].x + v[i].y + v[i].z + v[i].w;
        s2 += v[i].x * v[i].x + v[i].y * v[i].y + v[i].z * v[i].z + v[i].w * v[i].w;
    }
    blockReduce2(s, s2, sbuf);
    float mean = s * (1.f / HID);
    float var = s2 * (1.f / HID) - mean * mean;
    float rstd = rsqrtf(var + EPSF);
    float4* orow = (float4*)(o + (size_t)row * HID);
    uint2* hrow = (uint2*)(dh + (size_t)row * HID);
    uint2* lrow = (uint2*)(dl + (size_t)row * HID);
    const float4* sh4 = (const float4*)sh;
    const float4* sc4 = (const float4*)sc;
#pragma unroll
    for (int i = 0; i < 3; ++i) {
        int c = t + i * 256;
        float4 scv = sc4[c], shv = sh4[c], r;
        r.x = (v[i].x - mean) * rstd * (1.f + scv.x) + shv.x;
        r.y = (v[i].y - mean) * rstd * (1.f + scv.y) + shv.y;
        r.z = (v[i].z - mean) * rstd * (1.f + scv.z) + shv.z;
        r.w = (v[i].w - mean) * rstd * (1.f + scv.w) + shv.w;
        orow[c] = r;
        __half h[4], l[4];
        float rv[4] = {r.x, r.y, r.z, r.w};
#pragma unroll
        for (int j = 0; j < 4; ++j) {
            h[j] = __float2half_rn(rv[j]);
            l[j] = __float2half_rn(rv[j] - __half2float(h[j]));
        }
        hrow[c] = *(uint2*)h;
        lrow[c] = *(uint2*)l;
    }
}

__global__ void __launch_bounds__(256) tgemm2(const float* __restrict__ A,
                                              const float* __restrict__ LD,
                                              float* __restrict__ T, int K) {
    __shared__ float Ls[64 * 32];
    __shared__ float As[32 * 68];
    int tid = threadIdx.x, lane = tid & 31, w = tid >> 5;
    int bm = blockIdx.x * 32;
    float acc[4] = {0.f, 0.f, 0.f, 0.f};
    for (int k0 = 0; k0 < K; k0 += 64) {
        __syncthreads();
#pragma unroll
        for (int j = 0; j < 8; ++j) {
            int i = tid + j * 256;
            Ls[i] = LD[(size_t)(k0 + (i >> 5)) * 32 + (i & 31)];
        }
#pragma unroll
        for (int j = 0; j < 8; ++j) {
            int i = tid + j * 256;
            int r = i >> 6, c = i & 63;
            As[r * 68 + c] = A[(size_t)(bm + r) * K + k0 + c];
        }
        __syncthreads();
#pragma unroll 8
        for (int kk = 0; kk < 64; ++kk) {
            float ldv = Ls[kk * 32 + lane];
#pragma unroll
            for (int i = 0; i < 4; ++i) acc[i] += As[(w * 4 + i) * 68 + kk] * ldv;
        }
    }
#pragma unroll
    for (int i = 0; i < 4; ++i) T[(size_t)(bm + w * 4 + i) * 32 + lane] = acc[i];
}

__global__ void __launch_bounds__(64) rmsrope(const float* __restrict__ qkv,
                                              const float* __restrict__ wq,
                                              const float* __restrict__ wk,
                                              const float* __restrict__ pe, int loff,
                                              float* __restrict__ Q, float* __restrict__ K,
                                              float* __restrict__ V) {
    __shared__ float sbuf[4];
    int row = blockIdx.x, h = blockIdx.y, p = threadIdx.x;
    int l = loff + row;
    const float* base = qkv + (size_t)row * (3 * HID) + h * HD;
    float q0 = base[2 * p], q1 = base[2 * p + 1];
    float k0 = base[HID + 2 * p], k1 = base[HID + 2 * p + 1];
    float sq = q0 * q0 + q1 * q1, sk = k0 * k0 + k1 * k1;
#pragma unroll
    for (int o = 16; o; o >>= 1) {
        sq += __shfl_xor_sync(0xffffffffu, sq, o);
        sk += __shfl_xor_sync(0xffffffffu, sk, o);
    }
    int w = p >> 5;
    if ((p & 31) == 0) { sbuf[w] = sq; sbuf[2 + w] = sk; }
    __syncthreads();
    sq = sbuf[0] + sbuf[1];
    sk = sbuf[2] + sbuf[3];
    float rq = rsqrtf(sq * (1.f / HD) + EPSF);
    float rk = rsqrtf(sk * (1.f / HD) + EPSF);
    q0 *= rq * wq[2 * p]; q1 *= rq * wq[2 * p + 1];
    k0 *= rk * wk[2 * p]; k1 *= rk * wk[2 * p + 1];
    float4 f = ((const float4*)(pe + (size_t)l * 256))[p];
    size_t ob = (size_t)l * HID + h * HD;
    Q[ob + 2 * p] = f.x * q0 + f.y * q1;
    Q[ob + 2 * p + 1] = f.z * q0 + f.w * q1;
    K[ob + 2 * p] = f.x * k0 + f.y * k1;
    K[ob + 2 * p + 1] = f.z * k0 + f.w * k1;
    V[ob + 2 * p] = base[2 * HID + 2 * p];
    V[ob + 2 * p + 1] = base[2 * HID + 2 * p + 1];
}

#define FLASH_SMEM ((3 * 64 * 132 + 64 * 65) * 4)
__global__ void __launch_bounds__(256) flash(const float* __restrict__ Qg,
                                             const float* __restrict__ Kg,
                                             const float* __restrict__ Vg,
                                             float* __restrict__ Og,
                                             __half* __restrict__ Dh,
                                             __half* __restrict__ Dl) {
    extern __shared__ float smf[];
    float* Qs = smf;
    float* Ks = Qs + 64 * 132;
    float* Vs = Ks + 64 * 132;
    float* Ps = Vs + 64 * 132;
    int h = blockIdx.y;
    int qb = blockIdx.x * 64;
    int t = threadIdx.x, r = t >> 2, g = t & 3;
    const float scale = 0.08838834764831845f;

    for (int i = t; i < 64 * 32; i += 256) {
        int rr = i >> 5, c = i & 31;
        float4 qv = ((const float4*)(Qg + (size_t)(qb + rr) * HID + h * HD))[c];
        qv.x *= scale; qv.y *= scale; qv.z *= scale; qv.w *= scale;
        ((float4*)Qs)[rr * 33 + c] = qv;
    }
    float m = -1e30f, lsum = 0.f;
    float4 acc[8];
#pragma unroll
    for (int w = 0; w < 8; ++w) acc[w] = make_float4(0.f, 0.f, 0.f, 0.f);

    for (int kt = 0; kt < L_TOT; kt += 64) {
        __syncthreads();
        for (int i = t; i < 64 * 32; i += 256) {
            int rr = i >> 5, c = i & 31;
            ((float4*)Ks)[rr * 33 + c] = ((const float4*)(Kg + (size_t)(kt + rr) * HID + h * HD))[c];
            ((float4*)Vs)[rr * 33 + c] = ((const float4*)(Vg + (size_t)(kt + rr) * HID + h * HD))[c];
        }
        __syncthreads();

        float s[16];
#pragma unroll
        for (int jj = 0; jj < 16; ++jj) s[jj] = 0.f;
#pragma unroll 8
        for (int d4 = 0; d4 < 32; ++d4) {
            float4 qv = ((const float4*)Qs)[r * 33 + d4];
#pragma unroll
            for (int jj = 0; jj < 16; ++jj) {
                float4 kv = ((const float4*)Ks)[(g + 4 * jj) * 33 + d4];
                s[jj] += qv.x * kv.x + qv.y * kv.y + qv.z * kv.z + qv.w * kv.w;
            }
        }
        float tm = s[0];
#pragma unroll
        for (int jj = 1; jj < 16; ++jj) tm = fmaxf(tm, s[jj]);
        tm = fmaxf(tm, __shfl_xor_sync(0xffffffffu, tm, 1));
        tm = fmaxf(tm, __shfl_xor_sync(0xffffffffu, tm, 2));
        float mn = fmaxf(m, tm);
        float corr = __expf(m - mn);
        float ps = 0.f;
#pragma unroll
        for (int jj = 0; jj < 16; ++jj) {
            float pv = __expf(s[jj] - mn);
            Ps[r * 65 + g + 4 * jj] = pv;
            ps += pv;
        }
        ps += __shfl_xor_sync(0xffffffffu, ps, 1);
        ps += __shfl_xor_sync(0xffffffffu, ps, 2);
        lsum = lsum * corr + ps;
        m = mn;
#pragma unroll
        for (int w = 0; w < 8; ++w) {
            acc[w].x *= corr; acc[w].y *= corr; acc[w].z *= corr; acc[w].w *= corr;
        }
        __syncthreads();
#pragma unroll 4
        for (int j = 0; j < 64; ++j) {
            float pv = Ps[r * 65 + j];
#pragma unroll
            for (int w = 0; w < 8; ++w) {
                float4 vv = ((const float4*)Vs)[j * 33 + g + 4 * w];
                acc[w].x += pv * vv.x; acc[w].y += pv * vv.y;
                acc[w].z += pv * vv.z; acc[w].w += pv * vv.w;
            }
        }
    }
    float inv = 1.f / lsum;
    size_t orow = (size_t)(qb + r) * HID + h * HD;
#pragma unroll
    for (int w = 0; w < 8; ++w) {
        float4 o;
        o.x = acc[w].x * inv; o.y = acc[w].y * inv;
        o.z = acc[w].z * inv; o.w = acc[w].w * inv;
        ((float4*)(Og + orow))[g + 4 * w] = o;
        __half hh[4], ll[4];
        float ov[4] = {o.x, o.y, o.z, o.w};
#pragma unroll
        for (int j = 0; j < 4; ++j) {
            hh[j] = __float2half_rn(ov[j]);
            ll[j] = __float2half_rn(ov[j] - __half2float(hh[j]));
        }
        ((uint2*)(Dh + orow))[g + 4 * w] = *(uint2*)hh;
        ((uint2*)(Dl + orow))[g + 4 * w] = *(uint2*)ll;
    }
}

// ---------------- host ----------------
extern "C" void kernel_launch(void* const* d_in, const int* in_sizes, int n_in,
                              void* d_out, int out_size) {
    const float* img = (const float*)d_in[0];
    const float* txt = (const float*)d_in[1];
    const float* vec = (const float*)d_in[2];
    const float* pe = (const float*)d_in[3];
    const float* mod_w = (const float*)d_in[4];
    const float* mod_b = (const float*)d_in[5];
    const float* qkv_w = (const float*)d_in[6];
    const float* qkv_b = (const float*)d_in[7];
    const float* qkv_ld = (const float*)d_in[8];
    const float* qkv_lu = (const float*)d_in[9];
    const float* rmsq_w = (const float*)d_in[10];
    const float* rmsk_w = (const float*)d_in[11];
    const float* proj_w = (const float*)d_in[12];
    const float* proj_b = (const float*)d_in[13];
    const float* proj_ld = (const float*)d_in[14];
    const float* proj_lu = (const float*)d_in[15];
    const float* mlp0_w = (const float*)d_in[16];
    const float* mlp0_b = (const float*)d_in[17];
    const float* mlp0_ld = (const float*)d_in[18];
    const float* mlp0_lu = (const float*)d_in[19];
    const float* mlp2_w = (const float*)d_in[20];
    const float* mlp2_b = (const float*)d_in[21];
    const float* mlp2_ld = (const float*)d_in[22];
    const float* mlp2_lu = (const float*)d_in[23];
    float* out = (float*)d_out;

    float *sv, *mod, *xm, *tb, *qkv, *q, *k, *v, *attn, *x1, *hb;
    __half *wq16, *wp16, *w016, *w216, *a2h, *a2l, *f2h, *f2l, *b2h, *b2l, *t2h, *t2l, *lu2h;
    cudaGetSymbolAddress((void**)&sv, g_sv);
    cudaGetSymbolAddress((void**)&mod, g_mod);
    cudaGetSymbolAddress((void**)&xm, g_xm);
    cudaGetSymbolAddress((void**)&tb, g_t);
    cudaGetSymbolAddress((void**)&qkv, g_qkv);
    cudaGetSymbolAddress((void**)&q, g_q);
    cudaGetSymbolAddress((void**)&k, g_k);
    cudaGetSymbolAddress((void**)&v, g_v);
    cudaGetSymbolAddress((void**)&attn, g_attn);
    cudaGetSymbolAddress((void**)&x1, g_x1);
    cudaGetSymbolAddress((void**)&hb, g_h);
    cudaGetSymbolAddress((void**)&wq16, g_wq16);
    cudaGetSymbolAddress((void**)&wp16, g_wp16);
    cudaGetSymbolAddress((void**)&w016, g_w016);
    cudaGetSymbolAddress((void**)&w216, g_w216);
    cudaGetSymbolAddress((void**)&a2h, g_a2h);
    cudaGetSymbolAddress((void**)&a2l, g_a2l);
    cudaGetSymbolAddress((void**)&f2h, g_f2h);
    cudaGetSymbolAddress((void**)&f2l, g_f2l);
    cudaGetSymbolAddress((void**)&b2h, g_b2h);
    cudaGetSymbolAddress((void**)&b2l, g_b2l);
    cudaGetSymbolAddress((void**)&t2h, g_t2h);
    cudaGetSymbolAddress((void**)&t2l, g_t2l);
    cudaGetSymbolAddress((void**)&lu2h, g_lu2h);

    cudaFuncSetAttribute(flash, cudaFuncAttributeMaxDynamicSharedMemorySize, FLASH_SMEM);
    cudaFuncSetAttribute(gemm16<0>, cudaFuncAttributeMaxDynamicSharedMemorySize, GEMM_SMEM);
    cudaFuncSetAttribute(gemm16<1>, cudaFuncAttributeMaxDynamicSharedMemorySize, GEMM_SMEM);
    cudaFuncSetAttribute(gemm16<2>, cudaFuncAttributeMaxDynamicSharedMemorySize, GEMM_SMEM);

    silu_kernel<<<(HID + 255) / 256, 256>>>(vec, sv);
    gemv_mod<<<2 * 6 * HID, 128>>>(mod_w, mod_b, sv, mod);

    // weight conversions (fp16 single)
    convH16<<<(int)((2 * QKV_SZ / 4 + 255) / 256), 256>>>(qkv_w, wq16, 2 * QKV_SZ / 4);
    convH16<<<(int)((2 * PRJ_SZ / 4 + 255) / 256), 256>>>(proj_w, wp16, 2 * PRJ_SZ / 4);
    convH16<<<(int)((2 * MLP_SZ / 4 + 255) / 256), 256>>>(mlp0_w, w016, 2 * MLP_SZ / 4);
    convH16<<<(int)((2 * MLP_SZ / 4 + 255) / 256), 256>>>(mlp2_w, w216, 2 * MLP_SZ / 4);

    // pre(): s=0 img, s=1 txt
    for (int s = 0; s < 2; ++s) {
        const float* x = s == 0 ? img : txt;
        int M = s == 0 ? IMGL : TXTL;
        int loff = s == 0 ? TXTL : 0;
        const float* mm = mod + (size_t)s * 6 * HID;
        ln_modH<<<M, 256>>>(x, mm + 0 * HID, mm + 1 * HID, xm, a2h, a2l);
        tgemm2<<<M / 32, 256>>>(xm, qkv_ld + (size_t)s * HID * RANK, tb, HID);
        convHL16<<<(M * RANK / 4 + 255) / 256, 256>>>(tb, t2h, t2l, (size_t)M * RANK / 4);
        convLU16<<<(9216 * 32 + 255) / 256, 256>>>(qkv_lu + (size_t)s * RANK * 9216, lu2h, 9216);
        dim3 gq(M / 128, 9216 / 128);
        gemm16<0><<<gq, 256, GEMM_SMEM>>>(a2h, a2l, wq16 + s * QKV_SZ, t2h, t2l, lu2h,
                                          qkv_b + (size_t)s * 9216, nullptr, nullptr, qkv,
                                          nullptr, nullptr, M, 9216, HID);
        dim3 g2(M, HEADS);
        rmsrope<<<g2, 64>>>(qkv, rmsq_w + (size_t)s * HD, rmsk_w + (size_t)s * HD, pe, loff, q, k, v);
    }

    dim3 gf(L_TOT / 64, HEADS);
    flash<<<gf, 256, FLASH_SMEM>>>(q, k, v, attn, f2h, f2l);

    // post(): s=0 img (rows 512..), s=1 txt (rows 0..512)
    for (int s = 0; s < 2; ++s) {
        const float* x = s == 0 ? img : txt;
        int M = s == 0 ? IMGL : TXTL;
        int roff = s == 0 ? TXTL : 0;
        const float* a = attn + (size_t)roff * HID;
        const float* mm = mod + (size_t)s * 6 * HID;
        float* outp = out + (size_t)roff * HID;

        // x1 = x + g1 * svdq(a, proj)
        tgemm2<<<M / 32, 256>>>(a, proj_ld + (size_t)s * HID * RANK, tb, HID);
        convHL16<<<(M * RANK / 4 + 255) / 256, 256>>>(tb, t2h, t2l, (size_t)M * RANK / 4);
        convLU16<<<(HID * 32 + 255) / 256, 256>>>(proj_lu + (size_t)s * RANK * HID, lu2h, HID);
        dim3 gp(M / 128, HID / 128);
        gemm16<1><<<gp, 256, GEMM_SMEM>>>(f2h + (size_t)roff * HID, f2l + (size_t)roff * HID,
                                          wp16 + s * PRJ_SZ, t2h, t2l, lu2h,
                                          proj_b + (size_t)s * HID, x, mm + 2 * HID, x1,
                                          nullptr, nullptr, M, HID, HID);

        // h = gelu(svdq(ln_mod(x1), mlp0))
        ln_modH<<<M, 256>>>(x1, mm + 3 * HID, mm + 4 * HID, xm, a2h, a2l);
        tgemm2<<<M / 32, 256>>>(xm, mlp0_ld + (size_t)s * HID * RANK, tb, HID);
        convHL16<<<(M * RANK / 4 + 255) / 256, 256>>>(tb, t2h, t2l, (size_t)M * RANK / 4);
        convLU16<<<(MLPD * 32 + 255) / 256, 256>>>(mlp0_lu + (size_t)s * RANK * MLPD, lu2h, MLPD);
        dim3 gm0(M / 128, MLPD / 128);
        gemm16<2><<<gm0, 256, GEMM_SMEM>>>(a2h, a2l, w016 + s * MLP_SZ, t2h, t2l, lu2h,
                                           mlp0_b + (size_t)s * MLPD, nullptr, nullptr, hb,
                                           b2h, b2l, M, MLPD, HID);

        // out = x1 + g2 * svdq(h, mlp2)
        tgemm2<<<M / 32, 256>>>(hb, mlp2_ld + (size_t)s * MLPD * RANK, tb, MLPD);
        convHL16<<<(M * RANK / 4 + 255) / 256, 256>>>(tb, t2h, t2l, (size_t)M * RANK / 4);
        convLU16<<<(HID * 32 + 255) / 256, 256>>>(mlp2_lu + (size_t)s * RANK * HID, lu2h, HID);
        dim3 gm2(M / 128, HID / 128);
        gemm16<1><<<gm2, 256, GEMM_SMEM>>>(b2h, b2l, w216 + s * MLP_SZ, t2h, t2l, lu2h,
                                           mlp2_b + (size_t)s * HID, x1, mm + 5 * HID, outp,
                                           nullptr, nullptr, M, HID, MLPD);
    }
}

// round 13
// speedup vs baseline: 1.0035x; 1.0014x over previous
#include <cuda_runtime.h>
#include <cuda_bf16.h>
#include <cuda_fp16.h>
#include <math.h>

#define HID 3072
#define HEADS 24
#define HD 128
#define MLPD 12288
#define RANK 32
#define TXTL 512
#define IMGL 2048
#define L_TOT 2560
#define EPSF 1e-6f

#define QKV_SZ 28311552ULL
#define PRJ_SZ 9437184ULL
#define MLP_SZ 37748736ULL

// ---------------- device scratch ----------------
__device__ __align__(16) float g_sv[HID];
__device__ __align__(16) float g_mod[2 * 6 * HID];
__device__ __align__(16) float g_xm[(size_t)L_TOT * HID];
__device__ __align__(16) float g_t[(size_t)L_TOT * RANK];
__device__ __align__(16) float g_qkv[(size_t)L_TOT * 3 * HID];
__device__ __align__(16) float g_q[(size_t)L_TOT * HID];
__device__ __align__(16) float g_k[(size_t)L_TOT * HID];
__device__ __align__(16) float g_v[(size_t)L_TOT * HID];
__device__ __align__(16) float g_attn[(size_t)L_TOT * HID];
__device__ __align__(16) float g_x1[(size_t)L_TOT * HID];
__device__ __align__(16) float g_h[(size_t)IMGL * MLPD];

// fp16 weights (single, rounded)
__device__ __align__(16) __half g_wq16[2 * QKV_SZ];
__device__ __align__(16) __half g_wp16[2 * PRJ_SZ];
__device__ __align__(16) __half g_w016[2 * MLP_SZ];
__device__ __align__(16) __half g_w216[2 * MLP_SZ];
// fp16 activations (hi/lo)
__device__ __align__(16) __half g_a2h[(size_t)L_TOT * HID], g_a2l[(size_t)L_TOT * HID];
__device__ __align__(16) __half g_f2h[(size_t)L_TOT * HID], g_f2l[(size_t)L_TOT * HID];
__device__ __align__(16) __half g_b2h[(size_t)IMGL * MLPD], g_b2l[(size_t)IMGL * MLPD];
// lora
__device__ __align__(16) __half g_t2h[(size_t)L_TOT * RANK], g_t2l[(size_t)L_TOT * RANK];
__device__ __align__(16) __half g_lu2h[(size_t)MLPD * RANK];

// ---------------- asm helpers ----------------
__device__ __forceinline__ unsigned smem_u32(const void* p) {
    unsigned a;
    asm("{ .reg .u64 t; cvta.to.shared.u64 t, %1; cvt.u32.u64 %0, t; }" : "=r"(a) : "l"(p));
    return a;
}
__device__ __forceinline__ void ldmx4(unsigned (&r)[4], unsigned a) {
    asm volatile("ldmatrix.sync.aligned.m8n8.x4.shared.b16 {%0,%1,%2,%3}, [%4];"
                 : "=r"(r[0]), "=r"(r[1]), "=r"(r[2]), "=r"(r[3]) : "r"(a));
}
__device__ __forceinline__ void ldmx2(unsigned (&r)[2], unsigned a) {
    asm volatile("ldmatrix.sync.aligned.m8n8.x2.shared.b16 {%0,%1}, [%2];"
                 : "=r"(r[0]), "=r"(r[1]) : "r"(a));
}
__device__ __forceinline__ void mmaH(float (&d)[4], const unsigned (&a)[4], const unsigned (&b)[2]) {
    asm volatile("mma.sync.aligned.m16n8k16.row.col.f32.f16.f16.f32 "
                 "{%0,%1,%2,%3},{%4,%5,%6,%7},{%8,%9},{%0,%1,%2,%3};"
                 : "+f"(d[0]), "+f"(d[1]), "+f"(d[2]), "+f"(d[3])
                 : "r"(a[0]), "r"(a[1]), "r"(a[2]), "r"(a[3]), "r"(b[0]), "r"(b[1]));
}
__device__ __forceinline__ void cpa16(unsigned d, const void* s) {
    asm volatile("cp.async.cg.shared.global [%0], [%1], 16;" :: "r"(d), "l"(s));
}
__device__ __forceinline__ void cpcommit() { asm volatile("cp.async.commit_group;"); }
template <int N>
__device__ __forceinline__ void cpwait() { asm volatile("cp.async.wait_group %0;" :: "n"(N)); }

__device__ __forceinline__ float gelu2(float x) {
    float u = 0.7978845608028654f * (x + 0.044715f * x * x * x);
    float e = __expf(2.f * u);
    float th = 1.f - 2.f / (e + 1.f);
    return 0.5f * x * (1.f + th);
}

// ---------------- conversions ----------------
__global__ void __launch_bounds__(256) convH16(const float* __restrict__ src,
                                               __half* __restrict__ dh, size_t n4) {
    size_t idx = (size_t)blockIdx.x * 256 + threadIdx.x;
    if (idx >= n4) return;
    float4 v = ((const float4*)src)[idx];
    __half h[4] = {__float2half_rn(v.x), __float2half_rn(v.y),
                   __float2half_rn(v.z), __float2half_rn(v.w)};
    ((uint2*)dh)[idx] = *(uint2*)h;
}

__global__ void __launch_bounds__(256) convHL16(const float* __restrict__ src,
                                                __half* __restrict__ dh,
                                                __half* __restrict__ dl, size_t n4) {
    size_t idx = (size_t)blockIdx.x * 256 + threadIdx.x;
    if (idx >= n4) return;
    float4 v = ((const float4*)src)[idx];
    float vv[4] = {v.x, v.y, v.z, v.w};
    __half h[4], l[4];
#pragma unroll
    for (int i = 0; i < 4; ++i) {
        h[i] = __float2half_rn(vv[i]);
        l[i] = __float2half_rn(vv[i] - __half2float(h[i]));
    }
    ((uint2*)dh)[idx] = *(uint2*)h;
    ((uint2*)dl)[idx] = *(uint2*)l;
}

__global__ void __launch_bounds__(256) convLU16(const float* __restrict__ LU,
                                                __half* __restrict__ dh, int N) {
    int idx = blockIdx.x * 256 + threadIdx.x;
    if (idx >= N * 32) return;
    int n = idx >> 5, c = idx & 31;
    dh[(size_t)n * 32 + c] = __float2half_rn(LU[(size_t)c * N + n]);
}

// ---------------- fp16 2-pass split-precision GEMM ----------------
// stage (pitch 80B): Ah 0, Al 10240, Bh 20480 ; stage = 30720
#define STG_B 30720
#define GEMM_SMEM (2 * STG_B)

template <int MODE>
__global__ void __launch_bounds__(256, 2) gemm16(
    const __half* __restrict__ Ah, const __half* __restrict__ Al,
    const __half* __restrict__ Bh,
    const __half* __restrict__ Th, const __half* __restrict__ Tl,
    const __half* __restrict__ LUh,
    const float* __restrict__ bias, const float* __restrict__ RES,
    const float* __restrict__ GATE, float* __restrict__ C,
    __half* __restrict__ AoH, __half* __restrict__ AoL,
    int M, int N, int K) {
    extern __shared__ char sm[];
    unsigned sbase = smem_u32(sm);
    int tid = threadIdx.x, lane = tid & 31, wid = tid >> 5;
    int wm = wid >> 2, wn = wid & 3;
    int bm = blockIdx.x * 128, bn = blockIdx.y * 128;
    int KC = K >> 5, TOT = KC + 1;

    float acc[4][4][4];
#pragma unroll
    for (int a = 0; a < 4; ++a)
#pragma unroll
        for (int b = 0; b < 4; ++b)
#pragma unroll
            for (int c = 0; c < 4; ++c) acc[a][b][c] = 0.f;

#define LOAD_STAGE(cc)                                                                   \
    {                                                                                    \
        int c_ = (cc);                                                                   \
        unsigned sb_ = sbase + (c_ & 1) * STG_B;                                         \
        const char* bases_[3];                                                           \
        size_t rb_; int ko_;                                                             \
        if (c_ < KC) {                                                                   \
            bases_[0] = (const char*)Ah; bases_[1] = (const char*)Al;                    \
            bases_[2] = (const char*)Bh; rb_ = (size_t)K * 2; ko_ = c_ * 64;             \
        } else {                                                                         \
            bases_[0] = (const char*)Th; bases_[1] = (const char*)Tl;                    \
            bases_[2] = (const char*)LUh; rb_ = 64; ko_ = 0;                             \
        }                                                                                \
        _Pragma("unroll")                                                                \
        for (int j = 0; j < 6; ++j) {                                                    \
            int i = tid + j * 256;                                                       \
            int mat = i >> 9, r = (i >> 2) & 127, seg = i & 3;                           \
            int gr = (mat < 2 ? bm : bn) + r;                                            \
            const char* s_ = bases_[mat] + (size_t)gr * rb_ + ko_ + seg * 16;            \
            cpa16(sb_ + mat * 10240 + r * 80 + seg * 16, s_);                            \
        }                                                                                \
        cpcommit();                                                                      \
    }

    LOAD_STAGE(0);
    for (int c = 0; c < TOT; ++c) {
        if (c + 1 < TOT) { LOAD_STAGE(c + 1); cpwait<1>(); }
        else { cpwait<0>(); }
        __syncthreads();
        unsigned sb = sbase + (c & 1) * STG_B;
#pragma unroll
        for (int s = 0; s < 2; ++s) {
            unsigned ahf[4][4], alf[4][4];
#pragma unroll
            for (int mf = 0; mf < 4; ++mf) {
                unsigned row = wm * 64 + mf * 16 + (lane & 15);
                unsigned off = row * 80 + s * 32 + ((lane >> 4) << 4);
                ldmx4(ahf[mf], sb + off);
                ldmx4(alf[mf], sb + 10240 + off);
            }
#pragma unroll
            for (int nf = 0; nf < 4; ++nf) {
                unsigned brow = wn * 32 + nf * 8 + (lane & 7);
                unsigned bh2[2];
                ldmx2(bh2, sb + 20480 + brow * 80 + s * 32 + (((lane >> 3) & 1) << 4));
#pragma unroll
                for (int mf = 0; mf < 4; ++mf) {
                    mmaH(acc[mf][nf], ahf[mf], bh2);
                    mmaH(acc[mf][nf], alf[mf], bh2);
                }
            }
        }
        __syncthreads();
    }

    // epilogue
#pragma unroll
    for (int nf = 0; nf < 4; ++nf) {
        int gn = bn + wn * 32 + nf * 8 + (lane & 3) * 2;
        float b0 = bias[gn], b1 = bias[gn + 1];
        float g0 = 0.f, g1 = 0.f;
        if (MODE == 1) { g0 = GATE[gn]; g1 = GATE[gn + 1]; }
#pragma unroll
        for (int mf = 0; mf < 4; ++mf) {
            int gm = bm + wm * 64 + mf * 16 + (lane >> 2);
            float v0 = acc[mf][nf][0] + b0, v1 = acc[mf][nf][1] + b1;
            float v2 = acc[mf][nf][2] + b0, v3 = acc[mf][nf][3] + b1;
            if (MODE == 2) { v0 = gelu2(v0); v1 = gelu2(v1); v2 = gelu2(v2); v3 = gelu2(v3); }
            if (MODE == 1) {
                float2 r0 = *(const float2*)&RES[(size_t)gm * N + gn];
                float2 r1 = *(const float2*)&RES[(size_t)(gm + 8) * N + gn];
                v0 = r0.x + g0 * v0; v1 = r0.y + g1 * v1;
                v2 = r1.x + g0 * v2; v3 = r1.y + g1 * v3;
            }
            *(float2*)&C[(size_t)gm * N + gn] = make_float2(v0, v1);
            *(float2*)&C[(size_t)(gm + 8) * N + gn] = make_float2(v2, v3);
            if (MODE == 2) {
                __half h0 = __float2half_rn(v0), h1 = __float2half_rn(v1);
                __half h2 = __float2half_rn(v2), h3 = __float2half_rn(v3);
                *(__half2*)&AoH[(size_t)gm * N + gn] = __halves2half2(h0, h1);
                *(__half2*)&AoL[(size_t)gm * N + gn] = __halves2half2(
                    __float2half_rn(v0 - __half2float(h0)), __float2half_rn(v1 - __half2float(h1)));
                *(__half2*)&AoH[(size_t)(gm + 8) * N + gn] = __halves2half2(h2, h3);
                *(__half2*)&AoL[(size_t)(gm + 8) * N + gn] = __halves2half2(
                    __float2half_rn(v2 - __half2float(h2)), __float2half_rn(v3 - __half2float(h3)));
            }
        }
    }
}

// ---------------- small kernels ----------------
__device__ __forceinline__ void blockReduce2(float& a, float& b, float* sbuf) {
    int lane = threadIdx.x & 31, w = threadIdx.x >> 5;
    int nw = blockDim.x >> 5;
#pragma unroll
    for (int o = 16; o; o >>= 1) {
        a += __shfl_xor_sync(0xffffffffu, a, o);
        b += __shfl_xor_sync(0xffffffffu, b, o);
    }
    if (lane == 0) { sbuf[w] = a; sbuf[nw + w] = b; }
    __syncthreads();
    a = 0.f; b = 0.f;
    for (int i = 0; i < nw; ++i) { a += sbuf[i]; b += sbuf[nw + i]; }
    __syncthreads();
}

__global__ void silu_kernel(const float* __restrict__ v, float* __restrict__ o) {
    int i = blockIdx.x * 256 + threadIdx.x;
    if (i < HID) { float x = v[i]; o[i] = x / (1.f + __expf(-x)); }
}

__global__ void __launch_bounds__(128) gemv_mod(const float* __restrict__ w,
                                                const float* __restrict__ b,
                                                const float* __restrict__ sv,
                                                float* __restrict__ o) {
    __shared__ float sbuf[8];
    int n = blockIdx.x;
    const float4* wr = (const float4*)(w + (size_t)n * HID);
    const float4* vv = (const float4*)sv;
    int t = threadIdx.x;
    float s = 0.f;
#pragma unroll
    for (int i = 0; i < 6; ++i) {
        float4 a = wr[t + i * 128], c = vv[t + i * 128];
        s += a.x * c.x + a.y * c.y + a.z * c.z + a.w * c.w;
    }
    float dummy = 0.f;
    blockReduce2(s, dummy, sbuf);
    if (t == 0) o[n] = s + b[n];
}

// LN + modulation; fp16 hi/lo outputs
__global__ void __launch_bounds__(256) ln_modH(const float* __restrict__ x,
                                               const float* __restrict__ sh,
                                               const float* __restrict__ sc,
                                               float* __restrict__ o,
                                               __half* __restrict__ dh,
                                               __half* __restrict__ dl) {
    __shared__ float sbuf[16];
    int row = blockIdx.x, t = threadIdx.x;
    const float4* xr = (const float4*)(x + (size_t)row * HID);
    float4 v[3];
    float s = 0.f, s2 = 0.f;
#pragma unroll
    for (int i = 0; i < 3; ++i) {
        v[i] = xr[t + i * 256];
        s += v[i].x + v[i].y + v[i].z + v[i].w;
        s2 += v[i].x * v[i].x + v[i].y * v[i].y + v[i].z * v[i].z + v[i].w * v[i].w;
    }
    blockReduce2(s, s2, sbuf);
    float mean = s * (1.f / HID);
    float var = s2 * (1.f / HID) - mean * mean;
    float rstd = rsqrtf(var + EPSF);
    float4* orow = (float4*)(o + (size_t)row * HID);
    uint2* hrow = (uint2*)(dh + (size_t)row * HID);
    uint2* lrow = (uint2*)(dl + (size_t)row * HID);
    const float4* sh4 = (const float4*)sh;
    const float4* sc4 = (const float4*)sc;
#pragma unroll
    for (int i = 0; i < 3; ++i) {
        int c = t + i * 256;
        float4 scv = sc4[c], shv = sh4[c], r;
        r.x = (v[i].x - mean) * rstd * (1.f + scv.x) + shv.x;
        r.y = (v[i].y - mean) * rstd * (1.f + scv.y) + shv.y;
        r.z = (v[i].z - mean) * rstd * (1.f + scv.z) + shv.z;
        r.w = (v[i].w - mean) * rstd * (1.f + scv.w) + shv.w;
        orow[c] = r;
        __half h[4], l[4];
        float rv[4] = {r.x, r.y, r.z, r.w};
#pragma unroll
        for (int j = 0; j < 4; ++j) {
            h[j] = __float2half_rn(rv[j]);
            l[j] = __float2half_rn(rv[j] - __half2float(h[j]));
        }
        hrow[c] = *(uint2*)h;
        lrow[c] = *(uint2*)l;
    }
}

__global__ void __launch_bounds__(256) tgemm2(const float* __restrict__ A,
                                              const float* __restrict__ LD,
                                              float* __restrict__ T, int K) {
    __shared__ float Ls[64 * 32];
    __shared__ float As[32 * 68];
    int tid = threadIdx.x, lane = tid & 31, w = tid >> 5;
    int bm = blockIdx.x * 32;
    float acc[4] = {0.f, 0.f, 0.f, 0.f};
    for (int k0 = 0; k0 < K; k0 += 64) {
        __syncthreads();
#pragma unroll
        for (int j = 0; j < 8; ++j) {
            int i = tid + j * 256;
            Ls[i] = LD[(size_t)(k0 + (i >> 5)) * 32 + (i & 31)];
        }
#pragma unroll
        for (int j = 0; j < 8; ++j) {
            int i = tid + j * 256;
            int r = i >> 6, c = i & 63;
            As[r * 68 + c] = A[(size_t)(bm + r) * K + k0 + c];
        }
        __syncthreads();
#pragma unroll 8
        for (int kk = 0; kk < 64; ++kk) {
            float ldv = Ls[kk * 32 + lane];
#pragma unroll
            for (int i = 0; i < 4; ++i) acc[i] += As[(w * 4 + i) * 68 + kk] * ldv;
        }
    }
#pragma unroll
    for (int i = 0; i < 4; ++i) T[(size_t)(bm + w * 4 + i) * 32 + lane] = acc[i];
}

__global__ void __launch_bounds__(64) rmsrope(const float* __restrict__ qkv,
                                              const float* __restrict__ wq,
                                              const float* __restrict__ wk,
                                              const float* __restrict__ pe, int loff,
                                              float* __restrict__ Q, float* __restrict__ K,
                                              float* __restrict__ V) {
    __shared__ float sbuf[4];
    int row = blockIdx.x, h = blockIdx.y, p = threadIdx.x;
    int l = loff + row;
    const float* base = qkv + (size_t)row * (3 * HID) + h * HD;
    float q0 = base[2 * p], q1 = base[2 * p + 1];
    float k0 = base[HID + 2 * p], k1 = base[HID + 2 * p + 1];
    float sq = q0 * q0 + q1 * q1, sk = k0 * k0 + k1 * k1;
#pragma unroll
    for (int o = 16; o; o >>= 1) {
        sq += __shfl_xor_sync(0xffffffffu, sq, o);
        sk += __shfl_xor_sync(0xffffffffu, sk, o);
    }
    int w = p >> 5;
    if ((p & 31) == 0) { sbuf[w] = sq; sbuf[2 + w] = sk; }
    __syncthreads();
    sq = sbuf[0] + sbuf[1];
    sk = sbuf[2] + sbuf[3];
    float rq = rsqrtf(sq * (1.f / HD) + EPSF);
    float rk = rsqrtf(sk * (1.f / HD) + EPSF);
    q0 *= rq * wq[2 * p]; q1 *= rq * wq[2 * p + 1];
    k0 *= rk * wk[2 * p]; k1 *= rk * wk[2 * p + 1];
    float4 f = ((const float4*)(pe + (size_t)l * 256))[p];
    size_t ob = (size_t)l * HID + h * HD;
    Q[ob + 2 * p] = f.x * q0 + f.y * q1;
    Q[ob + 2 * p + 1] = f.z * q0 + f.w * q1;
    K[ob + 2 * p] = f.x * k0 + f.y * k1;
    K[ob + 2 * p + 1] = f.z * k0 + f.w * k1;
    V[ob + 2 * p] = base[2 * HID + 2 * p];
    V[ob + 2 * p + 1] = base[2 * HID + 2 * p + 1];
}

#define FLASH_SMEM ((3 * 64 * 132 + 64 * 65) * 4)
__global__ void __launch_bounds__(256) flash(const float* __restrict__ Qg,
                                             const float* __restrict__ Kg,
                                             const float* __restrict__ Vg,
                                             float* __restrict__ Og,
                                             __half* __restrict__ Dh,
                                             __half* __restrict__ Dl) {
    extern __shared__ float smf[];
    float* Qs = smf;
    float* Ks = Qs + 64 * 132;
    float* Vs = Ks + 64 * 132;
    float* Ps = Vs + 64 * 132;
    int h = blockIdx.y;
    int qb = blockIdx.x * 64;
    int t = threadIdx.x, r = t >> 2, g = t & 3;
    const float scale = 0.08838834764831845f;

    for (int i = t; i < 64 * 32; i += 256) {
        int rr = i >> 5, c = i & 31;
        float4 qv = ((const float4*)(Qg + (size_t)(qb + rr) * HID + h * HD))[c];
        qv.x *= scale; qv.y *= scale; qv.z *= scale; qv.w *= scale;
        ((float4*)Qs)[rr * 33 + c] = qv;
    }
    float m = -1e30f, lsum = 0.f;
    float4 acc[8];
#pragma unroll
    for (int w = 0; w < 8; ++w) acc[w] = make_float4(0.f, 0.f, 0.f, 0.f);

    for (int kt = 0; kt < L_TOT; kt += 64) {
        __syncthreads();
        for (int i = t; i < 64 * 32; i += 256) {
            int rr = i >> 5, c = i & 31;
            ((float4*)Ks)[rr * 33 + c] = ((const float4*)(Kg + (size_t)(kt + rr) * HID + h * HD))[c];
            ((float4*)Vs)[rr * 33 + c] = ((const float4*)(Vg + (size_t)(kt + rr) * HID + h * HD))[c];
        }
        __syncthreads();

        float s[16];
#pragma unroll
        for (int jj = 0; jj < 16; ++jj) s[jj] = 0.f;
#pragma unroll 8
        for (int d4 = 0; d4 < 32; ++d4) {
            float4 qv = ((const float4*)Qs)[r * 33 + d4];
#pragma unroll
            for (int jj = 0; jj < 16; ++jj) {
                float4 kv = ((const float4*)Ks)[(g + 4 * jj) * 33 + d4];
                s[jj] += qv.x * kv.x + qv.y * kv.y + qv.z * kv.z + qv.w * kv.w;
            }
        }
        float tm = s[0];
#pragma unroll
        for (int jj = 1; jj < 16; ++jj) tm = fmaxf(tm, s[jj]);
        tm = fmaxf(tm, __shfl_xor_sync(0xffffffffu, tm, 1));
        tm = fmaxf(tm, __shfl_xor_sync(0xffffffffu, tm, 2));
        float mn = fmaxf(m, tm);
        float corr = __expf(m - mn);
        float ps = 0.f;
#pragma unroll
        for (int jj = 0; jj < 16; ++jj) {
            float pv = __expf(s[jj] - mn);
            Ps[r * 65 + g + 4 * jj] = pv;
            ps += pv;
        }
        ps += __shfl_xor_sync(0xffffffffu, ps, 1);
        ps += __shfl_xor_sync(0xffffffffu, ps, 2);
        lsum = lsum * corr + ps;
        m = mn;
#pragma unroll
        for (int w = 0; w < 8; ++w) {
            acc[w].x *= corr; acc[w].y *= corr; acc[w].z *= corr; acc[w].w *= corr;
        }
        __syncthreads();
#pragma unroll 4
        for (int j = 0; j < 64; ++j) {
            float pv = Ps[r * 65 + j];
#pragma unroll
            for (int w = 0; w < 8; ++w) {
                float4 vv = ((const float4*)Vs)[j * 33 + g + 4 * w];
                acc[w].x += pv * vv.x; acc[w].y += pv * vv.y;
                acc[w].z += pv * vv.z; acc[w].w += pv * vv.w;
            }
        }
    }
    float inv = 1.f / lsum;
    size_t orow = (size_t)(qb + r) * HID + h * HD;
#pragma unroll
    for (int w = 0; w < 8; ++w) {
        float4 o;
        o.x = acc[w].x * inv; o.y = acc[w].y * inv;
        o.z = acc[w].z * inv; o.w = acc[w].w * inv;
        ((float4*)(Og + orow))[g + 4 * w] = o;
        __half hh[4], ll[4];
        float ov[4] = {o.x, o.y, o.z, o.w};
#pragma unroll
        for (int j = 0; j < 4; ++j) {
            hh[j] = __float2half_rn(ov[j]);
            ll[j] = __float2half_rn(ov[j] - __half2float(hh[j]));
        }
        ((uint2*)(Dh + orow))[g + 4 * w] = *(uint2*)hh;
        ((uint2*)(Dl + orow))[g + 4 * w] = *(uint2*)ll;
    }
}

// ---------------- host ----------------
extern "C" void kernel_launch(void* const* d_in, const int* in_sizes, int n_in,
                              void* d_out, int out_size) {
    const float* img = (const float*)d_in[0];
    const float* txt = (const float*)d_in[1];
    const float* vec = (const float*)d_in[2];
    const float* pe = (const float*)d_in[3];
    const float* mod_w = (const float*)d_in[4];
    const float* mod_b = (const float*)d_in[5];
    const float* qkv_w = (const float*)d_in[6];
    const float* qkv_b = (const float*)d_in[7];
    const float* qkv_ld = (const float*)d_in[8];
    const float* qkv_lu = (const float*)d_in[9];
    const float* rmsq_w = (const float*)d_in[10];
    const float* rmsk_w = (const float*)d_in[11];
    const float* proj_w = (const float*)d_in[12];
    const float* proj_b = (const float*)d_in[13];
    const float* proj_ld = (const float*)d_in[14];
    const float* proj_lu = (const float*)d_in[15];
    const float* mlp0_w = (const float*)d_in[16];
    const float* mlp0_b = (const float*)d_in[17];
    const float* mlp0_ld = (const float*)d_in[18];
    const float* mlp0_lu = (const float*)d_in[19];
    const float* mlp2_w = (const float*)d_in[20];
    const float* mlp2_b = (const float*)d_in[21];
    const float* mlp2_ld = (const float*)d_in[22];
    const float* mlp2_lu = (const float*)d_in[23];
    float* out = (float*)d_out;

    float *sv, *mod, *xm, *tb, *qkv, *q, *k, *v, *attn, *x1, *hb;
    __half *wq16, *wp16, *w016, *w216, *a2h, *a2l, *f2h, *f2l, *b2h, *b2l, *t2h, *t2l, *lu2h;
    cudaGetSymbolAddress((void**)&sv, g_sv);
    cudaGetSymbolAddress((void**)&mod, g_mod);
    cudaGetSymbolAddress((void**)&xm, g_xm);
    cudaGetSymbolAddress((void**)&tb, g_t);
    cudaGetSymbolAddress((void**)&qkv, g_qkv);
    cudaGetSymbolAddress((void**)&q, g_q);
    cudaGetSymbolAddress((void**)&k, g_k);
    cudaGetSymbolAddress((void**)&v, g_v);
    cudaGetSymbolAddress((void**)&attn, g_attn);
    cudaGetSymbolAddress((void**)&x1, g_x1);
    cudaGetSymbolAddress((void**)&hb, g_h);
    cudaGetSymbolAddress((void**)&wq16, g_wq16);
    cudaGetSymbolAddress((void**)&wp16, g_wp16);
    cudaGetSymbolAddress((void**)&w016, g_w016);
    cudaGetSymbolAddress((void**)&w216, g_w216);
    cudaGetSymbolAddress((void**)&a2h, g_a2h);
    cudaGetSymbolAddress((void**)&a2l, g_a2l);
    cudaGetSymbolAddress((void**)&f2h, g_f2h);
    cudaGetSymbolAddress((void**)&f2l, g_f2l);
    cudaGetSymbolAddress((void**)&b2h, g_b2h);
    cudaGetSymbolAddress((void**)&b2l, g_b2l);
    cudaGetSymbolAddress((void**)&t2h, g_t2h);
    cudaGetSymbolAddress((void**)&t2l, g_t2l);
    cudaGetSymbolAddress((void**)&lu2h, g_lu2h);

    cudaFuncSetAttribute(flash, cudaFuncAttributeMaxDynamicSharedMemorySize, FLASH_SMEM);
    cudaFuncSetAttribute(gemm16<0>, cudaFuncAttributeMaxDynamicSharedMemorySize, GEMM_SMEM);
    cudaFuncSetAttribute(gemm16<1>, cudaFuncAttributeMaxDynamicSharedMemorySize, GEMM_SMEM);
    cudaFuncSetAttribute(gemm16<2>, cudaFuncAttributeMaxDynamicSharedMemorySize, GEMM_SMEM);

    silu_kernel<<<(HID + 255) / 256, 256>>>(vec, sv);
    gemv_mod<<<2 * 6 * HID, 128>>>(mod_w, mod_b, sv, mod);

    // weight conversions (fp16 single)
    convH16<<<(int)((2 * QKV_SZ / 4 + 255) / 256), 256>>>(qkv_w, wq16, 2 * QKV_SZ / 4);
    convH16<<<(int)((2 * PRJ_SZ / 4 + 255) / 256), 256>>>(proj_w, wp16, 2 * PRJ_SZ / 4);
    convH16<<<(int)((2 * MLP_SZ / 4 + 255) / 256), 256>>>(mlp0_w, w016, 2 * MLP_SZ / 4);
    convH16<<<(int)((2 * MLP_SZ / 4 + 255) / 256), 256>>>(mlp2_w, w216, 2 * MLP_SZ / 4);

    // pre(): s=0 img, s=1 txt
    for (int s = 0; s < 2; ++s) {
        const float* x = s == 0 ? img : txt;
        int M = s == 0 ? IMGL : TXTL;
        int loff = s == 0 ? TXTL : 0;
        const float* mm = mod + (size_t)s * 6 * HID;
        ln_modH<<<M, 256>>>(x, mm + 0 * HID, mm + 1 * HID, xm, a2h, a2l);
        tgemm2<<<M / 32, 256>>>(xm, qkv_ld + (size_t)s * HID * RANK, tb, HID);
        convHL16<<<(M * RANK / 4 + 255) / 256, 256>>>(tb, t2h, t2l, (size_t)M * RANK / 4);
        convLU16<<<(9216 * 32 + 255) / 256, 256>>>(qkv_lu + (size_t)s * RANK * 9216, lu2h, 9216);
        dim3 gq(M / 128, 9216 / 128);
        gemm16<0><<<gq, 256, GEMM_SMEM>>>(a2h, a2l, wq16 + s * QKV_SZ, t2h, t2l, lu2h,
                                          qkv_b + (size_t)s * 9216, nullptr, nullptr, qkv,
                                          nullptr, nullptr, M, 9216, HID);
        dim3 g2(M, HEADS);
        rmsrope<<<g2, 64>>>(qkv, rmsq_w + (size_t)s * HD, rmsk_w + (size_t)s * HD, pe, loff, q, k, v);
    }

    dim3 gf(L_TOT / 64, HEADS);
    flash<<<gf, 256, FLASH_SMEM>>>(q, k, v, attn, f2h, f2l);

    // post(): s=0 img (rows 512..), s=1 txt (rows 0..512)
    for (int s = 0; s < 2; ++s) {
        const float* x = s == 0 ? img : txt;
        int M = s == 0 ? IMGL : TXTL;
        int roff = s == 0 ? TXTL : 0;
        const float* a = attn + (size_t)roff * HID;
        const float* mm = mod + (size_t)s * 6 * HID;
        float* outp = out + (size_t)roff * HID;

        // x1 = x + g1 * svdq(a, proj)
        tgemm2<<<M / 32, 256>>>(a, proj_ld + (size_t)s * HID * RANK, tb, HID);
        convHL16<<<(M * RANK / 4 + 255) / 256, 256>>>(tb, t2h, t2l, (size_t)M * RANK / 4);
        convLU16<<<(HID * 32 + 255) / 256, 256>>>(proj_lu + (size_t)s * RANK * HID, lu2h, HID);
        dim3 gp(M / 128, HID / 128);
        gemm16<1><<<gp, 256, GEMM_SMEM>>>(f2h + (size_t)roff * HID, f2l + (size_t)roff * HID,
                                          wp16 + s * PRJ_SZ, t2h, t2l, lu2h,
                                          proj_b + (size_t)s * HID, x, mm + 2 * HID, x1,
                                          nullptr, nullptr, M, HID, HID);

        // h = gelu(svdq(ln_mod(x1), mlp0))
        ln_modH<<<M, 256>>>(x1, mm + 3 * HID, mm + 4 * HID, xm, a2h, a2l);
        tgemm2<<<M / 32, 256>>>(xm, mlp0_ld + (size_t)s * HID * RANK, tb, HID);
        convHL16<<<(M * RANK / 4 + 255) / 256, 256>>>(tb, t2h, t2l, (size_t)M * RANK / 4);
        convLU16<<<(MLPD * 32 + 255) / 256, 256>>>(mlp0_lu + (size_t)s * RANK * MLPD, lu2h, MLPD);
        dim3 gm0(M / 128, MLPD / 128);
        gemm16<2><<<gm0, 256, GEMM_SMEM>>>(a2h, a2l, w016 + s * MLP_SZ, t2h, t2l, lu2h,
                                           mlp0_b + (size_t)s * MLPD, nullptr, nullptr, hb,
                                           b2h, b2l, M, MLPD, HID);

        // out = x1 + g2 * svdq(h, mlp2)
        tgemm2<<<M / 32, 256>>>(hb, mlp2_ld + (size_t)s * MLPD * RANK, tb, MLPD);
        convHL16<<<(M * RANK / 4 + 255) / 256, 256>>>(tb, t2h, t2l, (size_t)M * RANK / 4);
        convLU16<<<(HID * 32 + 255) / 256, 256>>>(mlp2_lu + (size_t)s * RANK * HID, lu2h, HID);
        dim3 gm2(M / 128, HID / 128);
        gemm16<1><<<gm2, 256, GEMM_SMEM>>>(b2h, b2l, w216 + s * MLP_SZ, t2h, t2l, lu2h,
                                           mlp2_b + (size_t)s * HID, x1, mm + 5 * HID, outp,
                                           nullptr, nullptr, M, HID, MLPD);
    }
}